// round 1
// baseline (speedup 1.0000x reference)
#include <cuda_runtime.h>
#include <cstddef>
#include <cmath>

#define SDIM 1024
#define BDIM 2
#define CS   768
#define CZ   128
#define HN   24
#define DD   32
#define EPSF 1e-5f
#define NEGINF -1000000000.0f

// ---------------- scratch (device globals; no allocation allowed) ----------------
__device__ float g_emb[BDIM * 3 * CS];                    // shift|scale|gate per batch
__device__ float g_bsn[(size_t)BDIM * SDIM * CS];         // modulated LN(bs)
__device__ float g_q[(size_t)BDIM * SDIM * CS];           // q raw -> rms'd in place
__device__ float g_k[(size_t)BDIM * SDIM * CS];
__device__ float g_v[(size_t)BDIM * SDIM * CS];
__device__ float g_zb[(size_t)HN * SDIM * SDIM];          // per-head z bias (H,S,S)
__device__ float g_cb[(size_t)BDIM * SDIM * SDIM];        // beta + mask bias (B,S,S)
__device__ float g_att[(size_t)BDIM * SDIM * CS];         // attention output (B,S,H*D)

// ---------------- 1. adaLN embedding: emb = silu(t) @ w_adaln + b ----------------
__global__ void adaln_kernel(const float* __restrict__ t, const float* __restrict__ w,
                             const float* __restrict__ b) {
    __shared__ float st[CS];
    int bb = blockIdx.y;
    for (int c = threadIdx.x; c < CS; c += 256) {
        float x = t[bb * CS + c];
        st[c] = x / (1.f + __expf(-x));
    }
    __syncthreads();
    int n = blockIdx.x * 256 + threadIdx.x;   // grid.x = 9 -> n in [0,2304)
    float acc = b[n];
#pragma unroll 4
    for (int c = 0; c < CS; c++) acc += st[c] * w[c * 3 * CS + n];
    g_emb[bb * 3 * CS + n] = acc;
}

// ---------------- 2. bs_norm = LN(bs)*(1+scale)+shift ----------------
__global__ void bsnorm_kernel(const float* __restrict__ bs) {
    int row = blockIdx.x;           // b*S + s
    int bb = row >> 10;             // S = 1024
    const float* x = bs + (size_t)row * CS;
    float v[3];
    float s = 0.f, s2 = 0.f;
#pragma unroll
    for (int i = 0; i < 3; i++) {
        v[i] = x[threadIdx.x + i * 256];
        s += v[i]; s2 += v[i] * v[i];
    }
    __shared__ float rs[8], rs2[8], mvar[2];
#pragma unroll
    for (int o = 16; o; o >>= 1) {
        s  += __shfl_xor_sync(~0u, s, o);
        s2 += __shfl_xor_sync(~0u, s2, o);
    }
    int lane = threadIdx.x & 31, warp = threadIdx.x >> 5;
    if (lane == 0) { rs[warp] = s; rs2[warp] = s2; }
    __syncthreads();
    if (threadIdx.x == 0) {
        float a = 0.f, c = 0.f;
#pragma unroll
        for (int i = 0; i < 8; i++) { a += rs[i]; c += rs2[i]; }
        float mu = a * (1.f / CS);
        mvar[0] = mu;
        mvar[1] = rsqrtf(c * (1.f / CS) - mu * mu + EPSF);
    }
    __syncthreads();
    float mu = mvar[0], rstd = mvar[1];
    const float* shift = g_emb + bb * 3 * CS;
    const float* scale = shift + CS;
#pragma unroll
    for (int i = 0; i < 3; i++) {
        int c = threadIdx.x + i * 256;
        g_bsn[(size_t)row * CS + c] = (v[i] - mu) * rstd * (1.f + scale[c]) + shift[c];
    }
}

// ---------------- 3/8. SGEMM 128x128 tile, 8x8 per thread ----------------
// C[M,N] = A[M,K] @ B[K,N]; optional epilogue: (acc + bias[n]) * gate[b*3CS + n]
__global__ void sgemm_kernel(const float* __restrict__ A, const float* __restrict__ B,
                             float* __restrict__ C, int M, int N, int K,
                             const float* __restrict__ bias, const float* __restrict__ gate) {
    __shared__ float As[8][128];
    __shared__ float Bs[8][128];
    int tid = threadIdx.x;
    int tx = tid & 15, ty = tid >> 4;
    int m0 = blockIdx.y * 128, n0 = blockIdx.x * 128;
    float acc[8][8];
#pragma unroll
    for (int i = 0; i < 8; i++)
#pragma unroll
        for (int j = 0; j < 8; j++) acc[i][j] = 0.f;

    int arow = tid >> 1, acol = (tid & 1) * 4;
    int brow = tid >> 5, bcol = (tid & 31) * 4;
    const float* Ap = A + (size_t)(m0 + arow) * K + acol;
    const float* Bp = B + (size_t)brow * N + n0 + bcol;

    for (int kt = 0; kt < K; kt += 8) {
        float4 a4 = *(const float4*)(Ap + kt);
        As[acol + 0][arow] = a4.x; As[acol + 1][arow] = a4.y;
        As[acol + 2][arow] = a4.z; As[acol + 3][arow] = a4.w;
        *(float4*)&Bs[brow][bcol] = *(const float4*)(Bp + (size_t)kt * N);
        __syncthreads();
#pragma unroll
        for (int kk = 0; kk < 8; kk++) {
            float a[8], bb[8];
            *(float4*)(a)     = *(const float4*)&As[kk][ty * 8];
            *(float4*)(a + 4) = *(const float4*)&As[kk][ty * 8 + 4];
            *(float4*)(bb)     = *(const float4*)&Bs[kk][tx * 8];
            *(float4*)(bb + 4) = *(const float4*)&Bs[kk][tx * 8 + 4];
#pragma unroll
            for (int i = 0; i < 8; i++)
#pragma unroll
                for (int j = 0; j < 8; j++) acc[i][j] += a[i] * bb[j];
        }
        __syncthreads();
    }
#pragma unroll
    for (int i = 0; i < 8; i++) {
        int m = m0 + ty * 8 + i;
        size_t off = (size_t)m * N + n0 + tx * 8;
        if (gate) {
            int bb = m >> 10;
            const float* gp = gate + bb * 3 * CS;
#pragma unroll
            for (int j = 0; j < 8; j++) {
                int n = n0 + tx * 8 + j;
                acc[i][j] = (acc[i][j] + bias[n]) * gp[n];
            }
        }
        *(float4*)&C[off]     = *(float4*)&acc[i][0];
        *(float4*)&C[off + 4] = *(float4*)&acc[i][4];
    }
}

// ---------------- 4. per-head RMS norm (in place), warp per (b,s,h) ----------------
__global__ void rms_kernel(float* x, const float* __restrict__ w, int nrows) {
    int gw = (blockIdx.x * blockDim.x + threadIdx.x) >> 5;
    int lane = threadIdx.x & 31;
    if (gw >= nrows) return;
    float* p = x + (size_t)gw * DD;
    float v = p[lane];
    float ss = v * v;
#pragma unroll
    for (int o = 16; o; o >>= 1) ss += __shfl_xor_sync(~0u, ss, o);
    p[lane] = v * rsqrtf(ss * (1.f / DD) + EPSF) * w[lane];
}

// ---------------- 5. z bias: LN(z[i,j,:]) @ w_z -> g_zb[h,i,j] ----------------
// block: (jt, i); 32 j-rows of 128 channels; warp->3 heads, lane->j
__global__ void zbias_kernel(const float* __restrict__ z, const float* __restrict__ lnw,
                             const float* __restrict__ lnb, const float* __restrict__ wz) {
    __shared__ float zt[32 * 132];     // 32 rows, stride 132 (pad) of C_Z=128
    __shared__ float wzT[HN * CZ];     // transposed w_z: [h][c]
    __shared__ float outs[32 * HN];
    __shared__ float lnws[CZ], lnbs[CZ];
    int i = blockIdx.y, j0 = blockIdx.x * 32;
    int tid = threadIdx.x, lane = tid & 31, warp = tid >> 5;

    for (int u = tid; u < CZ * HN; u += 256) {
        int c = u / HN, h = u - c * HN;
        wzT[h * CZ + c] = wz[u];
    }
    if (tid < CZ) { lnws[tid] = lnw[tid]; lnbs[tid] = lnb[tid]; }

    const float* zp = z + ((size_t)i * SDIM + j0) * CZ;
    for (int u = tid; u < 32 * 32; u += 256) {
        int r = u >> 5, c4 = u & 31;
        float4 v = ((const float4*)zp)[r * 32 + c4];
        zt[r * 132 + c4 * 4 + 0] = v.x; zt[r * 132 + c4 * 4 + 1] = v.y;
        zt[r * 132 + c4 * 4 + 2] = v.z; zt[r * 132 + c4 * 4 + 3] = v.w;
    }
    __syncthreads();

    // LayerNorm per row: warp handles 4 rows, lane handles 4 channels
#pragma unroll
    for (int rr = 0; rr < 4; rr++) {
        int r = warp * 4 + rr;
        float4 v = *(float4*)&zt[r * 132 + lane * 4];
        float s  = v.x + v.y + v.z + v.w;
        float s2 = v.x * v.x + v.y * v.y + v.z * v.z + v.w * v.w;
#pragma unroll
        for (int o = 16; o; o >>= 1) {
            s  += __shfl_xor_sync(~0u, s, o);
            s2 += __shfl_xor_sync(~0u, s2, o);
        }
        float mu = s * (1.f / CZ);
        float rstd = rsqrtf(s2 * (1.f / CZ) - mu * mu + EPSF);
        int c = lane * 4;
        v.x = (v.x - mu) * rstd * lnws[c + 0] + lnbs[c + 0];
        v.y = (v.y - mu) * rstd * lnws[c + 1] + lnbs[c + 1];
        v.z = (v.z - mu) * rstd * lnws[c + 2] + lnbs[c + 2];
        v.w = (v.w - mu) * rstd * lnws[c + 3] + lnbs[c + 3];
        *(float4*)&zt[r * 132 + lane * 4] = v;
    }
    __syncthreads();

    // tiny GEMM: outs[j][h] = sum_c zt[j][c]*wzT[h][c]; warp -> 3 heads, lane -> j
    {
        int h0 = warp * 3;
        float a0 = 0.f, a1 = 0.f, a2 = 0.f;
        const float* w0 = &wzT[(h0 + 0) * CZ];
        const float* w1 = &wzT[(h0 + 1) * CZ];
        const float* w2 = &wzT[(h0 + 2) * CZ];
        const float* zr = &zt[lane * 132];
#pragma unroll
        for (int c = 0; c < CZ; c += 4) {
            float4 zv  = *(const float4*)&zr[c];
            float4 wv0 = *(const float4*)&w0[c];
            float4 wv1 = *(const float4*)&w1[c];
            float4 wv2 = *(const float4*)&w2[c];
            a0 += zv.x * wv0.x + zv.y * wv0.y + zv.z * wv0.z + zv.w * wv0.w;
            a1 += zv.x * wv1.x + zv.y * wv1.y + zv.z * wv1.z + zv.w * wv1.w;
            a2 += zv.x * wv2.x + zv.y * wv2.y + zv.z * wv2.z + zv.w * wv2.w;
        }
        outs[lane * HN + h0 + 0] = a0;
        outs[lane * HN + h0 + 1] = a1;
        outs[lane * HN + h0 + 2] = a2;
    }
    __syncthreads();
    for (int o = tid; o < 32 * HN; o += 256) {
        int h = o >> 5, j = o & 31;
        g_zb[((size_t)h * SDIM + i) * SDIM + j0 + j] = outs[j * HN + h];
    }
}

// ---------------- 6. combined bias: cb = beta + (mask ? 0 : -1e9) ----------------
__global__ void cb_kernel(const float* __restrict__ beta, const int* __restrict__ mask) {
    size_t total = (size_t)BDIM * SDIM * SDIM;
    for (size_t idx = (size_t)blockIdx.x * 256 + threadIdx.x; idx < total;
         idx += (size_t)gridDim.x * 256) {
        size_t ij = idx & ((size_t)SDIM * SDIM - 1);
        g_cb[idx] = beta[idx] + (mask[ij] > 0 ? 0.f : NEGINF);
    }
}

// ---------------- 7. flash attention, 64x64 tiles, fused bias ----------------
__global__ void attn_kernel(const float* __restrict__ q, const float* __restrict__ k,
                            const float* __restrict__ v) {
    __shared__ float Qs[64][33], Ks[64][33], Vs[64][33];
    __shared__ float Ps[64][68];
    int bh = blockIdx.y, b = bh / HN, h = bh - b * HN;
    int i0 = blockIdx.x * 64;
    int tid = threadIdx.x, tx = tid & 15, ty = tid >> 4;
    const float sc = 0.17677669529663687f;   // 1/sqrt(32)

    const float* qp = q + (size_t)b * SDIM * CS + h * DD;
    const float* kp = k + (size_t)b * SDIM * CS + h * DD;
    const float* vp = v + (size_t)b * SDIM * CS + h * DD;
    const float* zbp = g_zb + (size_t)h * SDIM * SDIM;
    const float* cbp = g_cb + (size_t)b * SDIM * SDIM;

    for (int u = tid; u < 64 * 8; u += 256) {
        int r = u >> 3, c4 = u & 7;
        float4 vv = *(const float4*)(qp + (size_t)(i0 + r) * CS + c4 * 4);
        Qs[r][c4 * 4 + 0] = vv.x * sc; Qs[r][c4 * 4 + 1] = vv.y * sc;
        Qs[r][c4 * 4 + 2] = vv.z * sc; Qs[r][c4 * 4 + 3] = vv.w * sc;
    }
    float m[4], l[4], acc[4][2];
#pragma unroll
    for (int i = 0; i < 4; i++) { m[i] = -1e30f; l[i] = 0.f; acc[i][0] = 0.f; acc[i][1] = 0.f; }
    __syncthreads();

    for (int j0 = 0; j0 < SDIM; j0 += 64) {
        for (int u = tid; u < 64 * 8; u += 256) {
            int r = u >> 3, c4 = u & 7;
            float4 kv = *(const float4*)(kp + (size_t)(j0 + r) * CS + c4 * 4);
            Ks[r][c4 * 4 + 0] = kv.x; Ks[r][c4 * 4 + 1] = kv.y;
            Ks[r][c4 * 4 + 2] = kv.z; Ks[r][c4 * 4 + 3] = kv.w;
            float4 vv = *(const float4*)(vp + (size_t)(j0 + r) * CS + c4 * 4);
            Vs[r][c4 * 4 + 0] = vv.x; Vs[r][c4 * 4 + 1] = vv.y;
            Vs[r][c4 * 4 + 2] = vv.z; Vs[r][c4 * 4 + 3] = vv.w;
        }
        __syncthreads();

        float s[4][4];
#pragma unroll
        for (int i = 0; i < 4; i++) {
            size_t ro = (size_t)(i0 + ty * 4 + i) * SDIM + j0 + tx * 4;
            float4 zb4 = *(const float4*)(zbp + ro);
            float4 cb4 = *(const float4*)(cbp + ro);
            s[i][0] = zb4.x + cb4.x; s[i][1] = zb4.y + cb4.y;
            s[i][2] = zb4.z + cb4.z; s[i][3] = zb4.w + cb4.w;
        }
#pragma unroll
        for (int kk = 0; kk < DD; kk++) {
            float a[4], bq[4];
#pragma unroll
            for (int i = 0; i < 4; i++) a[i] = Qs[ty * 4 + i][kk];
#pragma unroll
            for (int j = 0; j < 4; j++) bq[j] = Ks[tx * 4 + j][kk];
#pragma unroll
            for (int i = 0; i < 4; i++)
#pragma unroll
                for (int j = 0; j < 4; j++) s[i][j] += a[i] * bq[j];
        }
#pragma unroll
        for (int i = 0; i < 4; i++) {
            float mx = fmaxf(fmaxf(s[i][0], s[i][1]), fmaxf(s[i][2], s[i][3]));
#pragma unroll
            for (int o = 8; o; o >>= 1) mx = fmaxf(mx, __shfl_xor_sync(~0u, mx, o));
            float mn = fmaxf(m[i], mx);
            float corr = __expf(m[i] - mn);
            float p0 = __expf(s[i][0] - mn), p1 = __expf(s[i][1] - mn);
            float p2 = __expf(s[i][2] - mn), p3 = __expf(s[i][3] - mn);
            float ls = p0 + p1 + p2 + p3;
#pragma unroll
            for (int o = 8; o; o >>= 1) ls += __shfl_xor_sync(~0u, ls, o);
            l[i] = l[i] * corr + ls;
            m[i] = mn;
            acc[i][0] *= corr; acc[i][1] *= corr;
            Ps[ty * 4 + i][tx * 4 + 0] = p0; Ps[ty * 4 + i][tx * 4 + 1] = p1;
            Ps[ty * 4 + i][tx * 4 + 2] = p2; Ps[ty * 4 + i][tx * 4 + 3] = p3;
        }
        __syncthreads();
#pragma unroll 8
        for (int kk = 0; kk < 64; kk++) {
            float v0 = Vs[kk][tx * 2], v1 = Vs[kk][tx * 2 + 1];
#pragma unroll
            for (int i = 0; i < 4; i++) {
                float p = Ps[ty * 4 + i][kk];
                acc[i][0] += p * v0; acc[i][1] += p * v1;
            }
        }
        __syncthreads();
    }
#pragma unroll
    for (int i = 0; i < 4; i++) {
        int qrow = i0 + ty * 4 + i;
        float inv = 1.f / l[i];
        size_t o = ((size_t)b * SDIM + qrow) * CS + h * DD + tx * 2;
        g_att[o] = acc[i][0] * inv;
        g_att[o + 1] = acc[i][1] * inv;
    }
}

// ---------------- launch ----------------
extern "C" void kernel_launch(void* const* d_in, const int* in_sizes, int n_in,
                              void* d_out, int out_size) {
    const float* bs      = (const float*)d_in[0];
    const float* z       = (const float*)d_in[1];
    const float* t       = (const float*)d_in[2];
    const float* beta    = (const float*)d_in[3];
    const int*   z_mask  = (const int*)d_in[4];
    const float* w_adaln = (const float*)d_in[5];
    const float* b_adaln = (const float*)d_in[6];
    const float* ln_z_w  = (const float*)d_in[7];
    const float* ln_z_b  = (const float*)d_in[8];
    const float* w_q     = (const float*)d_in[9];
    const float* w_k     = (const float*)d_in[10];
    const float* w_v     = (const float*)d_in[11];
    const float* w_z     = (const float*)d_in[12];
    const float* rms_q_w = (const float*)d_in[13];
    const float* rms_k_w = (const float*)d_in[14];
    const float* w_o     = (const float*)d_in[15];
    const float* b_o     = (const float*)d_in[16];
    float* out = (float*)d_out;

    float *p_bsn, *p_q, *p_k, *p_v, *p_att, *p_emb;
    cudaGetSymbolAddress((void**)&p_bsn, g_bsn);
    cudaGetSymbolAddress((void**)&p_q,   g_q);
    cudaGetSymbolAddress((void**)&p_k,   g_k);
    cudaGetSymbolAddress((void**)&p_v,   g_v);
    cudaGetSymbolAddress((void**)&p_att, g_att);
    cudaGetSymbolAddress((void**)&p_emb, g_emb);

    const int M = BDIM * SDIM;   // 2048

    adaln_kernel<<<dim3(9, BDIM), 256>>>(t, w_adaln, b_adaln);
    bsnorm_kernel<<<M, 256>>>(bs);

    sgemm_kernel<<<dim3(CS / 128, M / 128), 256>>>(p_bsn, w_q, p_q, M, CS, CS, nullptr, nullptr);
    sgemm_kernel<<<dim3(CS / 128, M / 128), 256>>>(p_bsn, w_k, p_k, M, CS, CS, nullptr, nullptr);
    sgemm_kernel<<<dim3(CS / 128, M / 128), 256>>>(p_bsn, w_v, p_v, M, CS, CS, nullptr, nullptr);

    int nrows = BDIM * SDIM * HN;    // 49152
    rms_kernel<<<(nrows * 32) / 256, 256>>>(p_q, rms_q_w, nrows);
    rms_kernel<<<(nrows * 32) / 256, 256>>>(p_k, rms_k_w, nrows);

    zbias_kernel<<<dim3(SDIM / 32, SDIM), 256>>>(z, ln_z_w, ln_z_b, w_z);
    cb_kernel<<<2048, 256>>>(beta, z_mask);

    attn_kernel<<<dim3(SDIM / 64, BDIM * HN), 256>>>(p_q, p_k, p_v);

    sgemm_kernel<<<dim3(CS / 128, M / 128), 256>>>(p_att, w_o, out, M, CS, CS,
                                                   b_o, p_emb + 2 * CS);
}

// round 2
// speedup vs baseline: 1.1061x; 1.1061x over previous
#include <cuda_runtime.h>
#include <cstddef>

#define SDIM 1024
#define BDIM 2
#define CS   768
#define CZ   128
#define HN   24
#define DD   32
#define EPSF 1e-5f
#define NEGINF -1000000000.0f
#define LOG2E 1.4426950408889634f

// ---------------- scratch ----------------
__device__ float g_emb[BDIM * 3 * CS];
__device__ float g_bsn[(size_t)BDIM * SDIM * CS];
__device__ float g_q[(size_t)BDIM * SDIM * CS];
__device__ float g_k[(size_t)BDIM * SDIM * CS];
__device__ float g_v[(size_t)BDIM * SDIM * CS];
__device__ float g_zb[(size_t)HN * SDIM * SDIM];   // pre-scaled by LOG2E
__device__ float g_cb[(size_t)BDIM * SDIM * SDIM]; // pre-scaled by LOG2E
__device__ float g_att[(size_t)BDIM * SDIM * CS];

// ---------------- f32x2 helpers ----------------
typedef unsigned long long u64;
__device__ __forceinline__ u64 ffma2(u64 a, u64 b, u64 c) {
    u64 d; asm("fma.rn.f32x2 %0,%1,%2,%3;" : "=l"(d) : "l"(a), "l"(b), "l"(c)); return d;
}
__device__ __forceinline__ u64 add2(u64 a, u64 b) {
    u64 d; asm("add.rn.f32x2 %0,%1,%2;" : "=l"(d) : "l"(a), "l"(b)); return d;
}
__device__ __forceinline__ u64 mul2(u64 a, u64 b) {
    u64 d; asm("mul.rn.f32x2 %0,%1,%2;" : "=l"(d) : "l"(a), "l"(b)); return d;
}
__device__ __forceinline__ u64 pk2(float a, float b) {
    u64 d; asm("mov.b64 %0,{%1,%2};" : "=l"(d) : "f"(a), "f"(b)); return d;
}
__device__ __forceinline__ float2 up2(u64 v) {
    float2 r; asm("mov.b64 {%0,%1},%2;" : "=f"(r.x), "=f"(r.y) : "l"(v)); return r;
}

// exp2 on FMA/ALU pipes (no MUFU). x <= 0 expected; err ~2e-6.
__device__ __forceinline__ float exp2_fast(float x) {
    x = fmaxf(x, -125.0f);
    float r  = x + 12582912.0f;              // round-to-nearest int
    float fl = r - 12582912.0f;
    float f  = x - fl;                       // [-0.5, 0.5]
    int   n  = __float_as_int(r) - 0x4B400000;
    float p  = 1.3333558146e-3f;
    p = fmaf(p, f, 9.6181291918e-3f);
    p = fmaf(p, f, 5.5504108664e-2f);
    p = fmaf(p, f, 2.4022650696e-1f);
    p = fmaf(p, f, 6.9314718056e-1f);
    p = fmaf(p, f, 1.0f);
    return p * __int_as_float((n + 127) << 23);
}

// ---------------- 1. adaLN ----------------
__global__ void adaln_kernel(const float* __restrict__ t, const float* __restrict__ w,
                             const float* __restrict__ b) {
    __shared__ float st[CS];
    int bb = blockIdx.y;
    for (int c = threadIdx.x; c < CS; c += 256) {
        float x = t[bb * CS + c];
        st[c] = x / (1.f + __expf(-x));
    }
    __syncthreads();
    int n = blockIdx.x * 256 + threadIdx.x;
    float acc = b[n];
#pragma unroll 4
    for (int c = 0; c < CS; c++) acc += st[c] * w[c * 3 * CS + n];
    g_emb[bb * 3 * CS + n] = acc;
}

// ---------------- 2. bs_norm ----------------
__global__ void bsnorm_kernel(const float* __restrict__ bs) {
    int row = blockIdx.x;
    int bb = row >> 10;
    const float* x = bs + (size_t)row * CS;
    float v[3];
    float s = 0.f, s2 = 0.f;
#pragma unroll
    for (int i = 0; i < 3; i++) {
        v[i] = x[threadIdx.x + i * 256];
        s += v[i]; s2 += v[i] * v[i];
    }
    __shared__ float rs[8], rs2[8], mvar[2];
#pragma unroll
    for (int o = 16; o; o >>= 1) {
        s  += __shfl_xor_sync(~0u, s, o);
        s2 += __shfl_xor_sync(~0u, s2, o);
    }
    int lane = threadIdx.x & 31, warp = threadIdx.x >> 5;
    if (lane == 0) { rs[warp] = s; rs2[warp] = s2; }
    __syncthreads();
    if (threadIdx.x == 0) {
        float a = 0.f, c = 0.f;
#pragma unroll
        for (int i = 0; i < 8; i++) { a += rs[i]; c += rs2[i]; }
        float mu = a * (1.f / CS);
        mvar[0] = mu;
        mvar[1] = rsqrtf(c * (1.f / CS) - mu * mu + EPSF);
    }
    __syncthreads();
    float mu = mvar[0], rstd = mvar[1];
    const float* shift = g_emb + bb * 3 * CS;
    const float* scale = shift + CS;
#pragma unroll
    for (int i = 0; i < 3; i++) {
        int c = threadIdx.x + i * 256;
        g_bsn[(size_t)row * CS + c] = (v[i] - mu) * rstd * (1.f + scale[c]) + shift[c];
    }
}

// ---------------- 3. SGEMM: 128x128, double-buffered, FFMA2 ----------------
// MODE 0: fused QKV (+RMS on q,k). MODE 1: out = (A@W0 + bias) * gate
template<int MODE>
__global__ __launch_bounds__(256, 2) void sgemm2(
    const float* __restrict__ A,
    const float* __restrict__ W0, const float* __restrict__ W1, const float* __restrict__ W2,
    float* __restrict__ O0, float* __restrict__ O1, float* __restrict__ O2,
    const float* __restrict__ rq, const float* __restrict__ rk,
    const float* __restrict__ bias) {
    __shared__ float As2[2][8][256];   // duplicated A: [kk][2*row+{0,1}]
    __shared__ float Bs[2][8][128];
    int tid = threadIdx.x, tx = tid & 15, ty = tid >> 4;
    int mat, nb;
    const float* B; float* O;
    if (MODE == 0) {
        mat = blockIdx.x / 6; nb = blockIdx.x % 6;
        B = (mat == 0) ? W0 : (mat == 1 ? W1 : W2);
        O = (mat == 0) ? O0 : (mat == 1 ? O1 : O2);
    } else { mat = 0; nb = blockIdx.x; B = W0; O = O0; }
    int m0 = blockIdx.y * 128, n0 = nb * 128;
    const int K = CS, N = CS;
    int arow = tid >> 1, acol = (tid & 1) * 4;
    int brow = tid >> 5, bcol = (tid & 31) * 4;
    const float* Ap = A + (size_t)(m0 + arow) * K + acol;
    const float* Bp = B + (size_t)brow * N + n0 + bcol;

    u64 acc[8][4];
#pragma unroll
    for (int i = 0; i < 8; i++)
#pragma unroll
        for (int j = 0; j < 4; j++) acc[i][j] = 0ULL;

    float4 a4 = *(const float4*)Ap;
    float4 b4 = *(const float4*)Bp;
    {
        float va[4] = {a4.x, a4.y, a4.z, a4.w};
#pragma unroll
        for (int w = 0; w < 4; w++)
            *(float2*)&As2[0][acol + w][2 * arow] = make_float2(va[w], va[w]);
        *(float4*)&Bs[0][brow][bcol] = b4;
    }
    __syncthreads();
    int p = 0;
    for (int kt = 8; ; kt += 8) {
        bool more = kt < K;
        if (more) {
            a4 = *(const float4*)(Ap + kt);
            b4 = *(const float4*)(Bp + (size_t)kt * N);
        }
#pragma unroll
        for (int kk = 0; kk < 8; kk++) {
            const float* ar = &As2[p][kk][ty * 16];
            ulonglong2 aA = *(const ulonglong2*)ar;
            ulonglong2 aB = *(const ulonglong2*)(ar + 4);
            ulonglong2 aC = *(const ulonglong2*)(ar + 8);
            ulonglong2 aD = *(const ulonglong2*)(ar + 12);
            const float* br = &Bs[p][kk][tx * 8];
            ulonglong2 bA = *(const ulonglong2*)br;
            ulonglong2 bB = *(const ulonglong2*)(br + 4);
            u64 av[8] = {aA.x, aA.y, aB.x, aB.y, aC.x, aC.y, aD.x, aD.y};
            u64 bv[4] = {bA.x, bA.y, bB.x, bB.y};
#pragma unroll
            for (int i = 0; i < 8; i++)
#pragma unroll
                for (int j = 0; j < 4; j++) acc[i][j] = ffma2(av[i], bv[j], acc[i][j]);
        }
        if (!more) break;
        {
            float va[4] = {a4.x, a4.y, a4.z, a4.w};
#pragma unroll
            for (int w = 0; w < 4; w++)
                *(float2*)&As2[p ^ 1][acol + w][2 * arow] = make_float2(va[w], va[w]);
            *(float4*)&Bs[p ^ 1][brow][bcol] = b4;
        }
        p ^= 1;
        __syncthreads();
    }

    float vout[8][8];
#pragma unroll
    for (int i = 0; i < 8; i++)
#pragma unroll
        for (int jp = 0; jp < 4; jp++) {
            float2 u = up2(acc[i][jp]);
            vout[i][2 * jp] = u.x; vout[i][2 * jp + 1] = u.y;
        }
    if (MODE == 0 && mat < 2) {
        const float* rw = (mat == 0) ? rq : rk;
        float w8[8];
#pragma unroll
        for (int j = 0; j < 8; j++) w8[j] = rw[(tx * 8 + j) & 31];
#pragma unroll
        for (int i = 0; i < 8; i++) {
            float ss = 0.f;
#pragma unroll
            for (int j = 0; j < 8; j++) ss += vout[i][j] * vout[i][j];
            ss += __shfl_xor_sync(~0u, ss, 1);
            ss += __shfl_xor_sync(~0u, ss, 2);
            float r = rsqrtf(ss * (1.f / DD) + EPSF);
#pragma unroll
            for (int j = 0; j < 8; j++) vout[i][j] *= r * w8[j];
        }
    }
    if (MODE == 1) {
#pragma unroll
        for (int i = 0; i < 8; i++) {
            int mrow = m0 + ty * 8 + i;
            const float* gp = g_emb + (mrow >> 10) * 3 * CS + 2 * CS;
#pragma unroll
            for (int j = 0; j < 8; j++) {
                int n = n0 + tx * 8 + j;
                vout[i][j] = (vout[i][j] + bias[n]) * gp[n];
            }
        }
    }
#pragma unroll
    for (int i = 0; i < 8; i++) {
        size_t off = (size_t)(m0 + ty * 8 + i) * N + n0 + tx * 8;
        *(float4*)&O[off]     = *(float4*)&vout[i][0];
        *(float4*)&O[off + 4] = *(float4*)&vout[i][4];
    }
}

// ---------------- 5. z bias (FFMA2 inner product, output *LOG2E) ----------------
__global__ void zbias_kernel(const float* __restrict__ z, const float* __restrict__ lnw,
                             const float* __restrict__ lnb, const float* __restrict__ wz) {
    __shared__ float zt[32 * 132];
    __shared__ float wzT[HN * CZ];
    __shared__ float outs[32 * HN];
    __shared__ float lnws[CZ], lnbs[CZ];
    int i = blockIdx.y, j0 = blockIdx.x * 32;
    int tid = threadIdx.x, lane = tid & 31, warp = tid >> 5;

    for (int u = tid; u < CZ * HN; u += 256) {
        int c = u / HN, h = u - c * HN;
        wzT[h * CZ + c] = wz[u];
    }
    if (tid < CZ) { lnws[tid] = lnw[tid]; lnbs[tid] = lnb[tid]; }

    const float* zp = z + ((size_t)i * SDIM + j0) * CZ;
    for (int u = tid; u < 32 * 32; u += 256) {
        int r = u >> 5, c4 = u & 31;
        float4 v = ((const float4*)zp)[r * 32 + c4];
        *(float4*)&zt[r * 132 + c4 * 4] = v;
    }
    __syncthreads();

#pragma unroll
    for (int rr = 0; rr < 4; rr++) {
        int r = warp * 4 + rr;
        float4 v = *(float4*)&zt[r * 132 + lane * 4];
        float s  = v.x + v.y + v.z + v.w;
        float s2 = v.x * v.x + v.y * v.y + v.z * v.z + v.w * v.w;
#pragma unroll
        for (int o = 16; o; o >>= 1) {
            s  += __shfl_xor_sync(~0u, s, o);
            s2 += __shfl_xor_sync(~0u, s2, o);
        }
        float mu = s * (1.f / CZ);
        float rstd = rsqrtf(s2 * (1.f / CZ) - mu * mu + EPSF);
        int c = lane * 4;
        v.x = (v.x - mu) * rstd * lnws[c + 0] + lnbs[c + 0];
        v.y = (v.y - mu) * rstd * lnws[c + 1] + lnbs[c + 1];
        v.z = (v.z - mu) * rstd * lnws[c + 2] + lnbs[c + 2];
        v.w = (v.w - mu) * rstd * lnws[c + 3] + lnbs[c + 3];
        *(float4*)&zt[r * 132 + lane * 4] = v;
    }
    __syncthreads();

    {
        int h0 = warp * 3;
        u64 a0 = 0ULL, a1 = 0ULL, a2 = 0ULL;
        const ulonglong2* zr = (const ulonglong2*)&zt[lane * 132];
        const ulonglong2* w0 = (const ulonglong2*)&wzT[(h0 + 0) * CZ];
        const ulonglong2* w1 = (const ulonglong2*)&wzT[(h0 + 1) * CZ];
        const ulonglong2* w2 = (const ulonglong2*)&wzT[(h0 + 2) * CZ];
#pragma unroll
        for (int c = 0; c < 32; c++) {
            ulonglong2 zp2 = zr[c];
            ulonglong2 p0 = w0[c], p1 = w1[c], p2 = w2[c];
            a0 = ffma2(zp2.x, p0.x, a0); a0 = ffma2(zp2.y, p0.y, a0);
            a1 = ffma2(zp2.x, p1.x, a1); a1 = ffma2(zp2.y, p1.y, a1);
            a2 = ffma2(zp2.x, p2.x, a2); a2 = ffma2(zp2.y, p2.y, a2);
        }
        float2 r0 = up2(a0), r1 = up2(a1), r2 = up2(a2);
        outs[lane * HN + h0 + 0] = (r0.x + r0.y) * LOG2E;
        outs[lane * HN + h0 + 1] = (r1.x + r1.y) * LOG2E;
        outs[lane * HN + h0 + 2] = (r2.x + r2.y) * LOG2E;
    }
    __syncthreads();
    for (int o = tid; o < 32 * HN; o += 256) {
        int h = o >> 5, j = o & 31;
        g_zb[((size_t)h * SDIM + i) * SDIM + j0 + j] = outs[j * HN + h];
    }
}

// ---------------- 6. combined bias (pre-scaled by LOG2E) ----------------
__global__ void cb_kernel(const float* __restrict__ beta, const int* __restrict__ mask) {
    size_t total = (size_t)BDIM * SDIM * SDIM;
    for (size_t idx = (size_t)blockIdx.x * 256 + threadIdx.x; idx < total;
         idx += (size_t)gridDim.x * 256) {
        size_t ij = idx & ((size_t)SDIM * SDIM - 1);
        g_cb[idx] = (beta[idx] + (mask[ij] > 0 ? 0.f : NEGINF)) * LOG2E;
    }
}

// ---------------- 7. flash attention, base-2 softmax, FFMA2 ----------------
__global__ __launch_bounds__(256, 2) void attn2(const float* __restrict__ q,
                                                const float* __restrict__ k,
                                                const float* __restrict__ v) {
    extern __shared__ float sm[];
    float* QT2 = sm;            // [32][128]  dup'd transposed Q * sc
    float* KT  = sm + 4096;     // [32][68]   transposed K
    float* VS2 = sm + 6272;     // [64][64]   dup'd V
    float* PT  = sm + 10368;    // [64][68]   transposed P
    int bh = blockIdx.y, b = bh / HN, h = bh - b * HN;
    int i0 = blockIdx.x * 64;
    int tid = threadIdx.x, tx = tid & 15, ty = tid >> 4;
    const float sc = 0.17677669529663687f * LOG2E;

    const float* qp = q + (size_t)b * SDIM * CS + h * DD;
    const float* kp = k + (size_t)b * SDIM * CS + h * DD;
    const float* vp = v + (size_t)b * SDIM * CS + h * DD;
    const float* zbp = g_zb + (size_t)h * SDIM * SDIM;
    const float* cbp = g_cb + (size_t)b * SDIM * SDIM;

    // load Q: duplicated, transposed, scaled
    for (int u = tid; u < 512; u += 256) {
        int r = u >> 3, c4 = u & 7;
        float4 t4 = *(const float4*)(qp + (size_t)(i0 + r) * CS + c4 * 4);
        int d0 = c4 * 4;
        *(float2*)&QT2[(d0 + 0) * 128 + 2 * r] = make_float2(t4.x * sc, t4.x * sc);
        *(float2*)&QT2[(d0 + 1) * 128 + 2 * r] = make_float2(t4.y * sc, t4.y * sc);
        *(float2*)&QT2[(d0 + 2) * 128 + 2 * r] = make_float2(t4.z * sc, t4.z * sc);
        *(float2*)&QT2[(d0 + 3) * 128 + 2 * r] = make_float2(t4.w * sc, t4.w * sc);
    }

    u64 acc[2][2] = {0ULL, 0ULL, 0ULL, 0ULL};
    float m[4], l[4];
#pragma unroll
    for (int i = 0; i < 4; i++) { m[i] = -1e30f; l[i] = 0.f; }

    for (int j0 = 0; j0 < SDIM; j0 += 64) {
        // load K (transposed) and V (duplicated)
        for (int u = tid; u < 512; u += 256) {
            int r = u >> 3, c4 = u & 7;
            float4 kv = *(const float4*)(kp + (size_t)(j0 + r) * CS + c4 * 4);
            KT[(c4 * 4 + 0) * 68 + r] = kv.x;
            KT[(c4 * 4 + 1) * 68 + r] = kv.y;
            KT[(c4 * 4 + 2) * 68 + r] = kv.z;
            KT[(c4 * 4 + 3) * 68 + r] = kv.w;
            float4 vv = *(const float4*)(vp + (size_t)(j0 + r) * CS + c4 * 4);
            *(float2*)&VS2[r * 64 + (c4 * 4 + 0) * 2] = make_float2(vv.x, vv.x);
            *(float2*)&VS2[r * 64 + (c4 * 4 + 1) * 2] = make_float2(vv.y, vv.y);
            *(float2*)&VS2[r * 64 + (c4 * 4 + 2) * 2] = make_float2(vv.z, vv.z);
            *(float2*)&VS2[r * 64 + (c4 * 4 + 3) * 2] = make_float2(vv.w, vv.w);
        }
        // init scores with bias (global loads, overlap with sync)
        u64 s[4][2];
#pragma unroll
        for (int i = 0; i < 4; i++) {
            size_t ro = (size_t)(i0 + ty * 4 + i) * SDIM + j0 + tx * 4;
            ulonglong2 zb2 = *(const ulonglong2*)(zbp + ro);
            ulonglong2 cb2 = *(const ulonglong2*)(cbp + ro);
            s[i][0] = add2(zb2.x, cb2.x);
            s[i][1] = add2(zb2.y, cb2.y);
        }
        __syncthreads();

        // QK^T: s packed along j
#pragma unroll 8
        for (int kk = 0; kk < DD; kk++) {
            const float* ar = &QT2[kk * 128 + ty * 8];
            ulonglong2 aA = *(const ulonglong2*)ar;      // (a0,a0),(a1,a1)
            ulonglong2 aB = *(const ulonglong2*)(ar + 4);
            ulonglong2 bA = *(const ulonglong2*)&KT[kk * 68 + tx * 4]; // (b0,b1),(b2,b3)
            s[0][0] = ffma2(aA.x, bA.x, s[0][0]); s[0][1] = ffma2(aA.x, bA.y, s[0][1]);
            s[1][0] = ffma2(aA.y, bA.x, s[1][0]); s[1][1] = ffma2(aA.y, bA.y, s[1][1]);
            s[2][0] = ffma2(aB.x, bA.x, s[2][0]); s[2][1] = ffma2(aB.x, bA.y, s[2][1]);
            s[3][0] = ffma2(aB.y, bA.x, s[3][0]); s[3][1] = ffma2(aB.y, bA.y, s[3][1]);
        }

        // online softmax (base 2)
        float corr[4];
#pragma unroll
        for (int i = 0; i < 4; i++) {
            float2 p0 = up2(s[i][0]), p1 = up2(s[i][1]);
            float mx = fmaxf(fmaxf(p0.x, p0.y), fmaxf(p1.x, p1.y));
#pragma unroll
            for (int o = 8; o; o >>= 1) mx = fmaxf(mx, __shfl_xor_sync(~0u, mx, o));
            float mn = fmaxf(m[i], mx);
            corr[i] = exp2_fast(m[i] - mn);
            m[i] = mn;
            float e0 = exp2_fast(p0.x - mn), e1 = exp2_fast(p0.y - mn);
            float e2 = exp2_fast(p1.x - mn), e3 = exp2_fast(p1.y - mn);
            float ls = e0 + e1 + e2 + e3;
#pragma unroll
            for (int o = 8; o; o >>= 1) ls += __shfl_xor_sync(~0u, ls, o);
            l[i] = l[i] * corr[i] + ls;
            int col = ty * 4 + i;
            PT[(tx * 4 + 0) * 68 + col] = e0;
            PT[(tx * 4 + 1) * 68 + col] = e1;
            PT[(tx * 4 + 2) * 68 + col] = e2;
            PT[(tx * 4 + 3) * 68 + col] = e3;
        }
        // rescale accumulators
        {
            u64 c01 = pk2(corr[0], corr[1]);
            u64 c23 = pk2(corr[2], corr[3]);
            acc[0][0] = mul2(acc[0][0], c01); acc[0][1] = mul2(acc[0][1], c01);
            acc[1][0] = mul2(acc[1][0], c23); acc[1][1] = mul2(acc[1][1], c23);
        }
        __syncthreads();

        // P @ V: acc packed along i
#pragma unroll 8
        for (int kk = 0; kk < 64; kk++) {
            ulonglong2 pp = *(const ulonglong2*)&PT[kk * 68 + ty * 4];  // (P0,P1),(P2,P3)
            ulonglong2 vv = *(const ulonglong2*)&VS2[kk * 64 + tx * 4]; // (v0,v0),(v1,v1)
            acc[0][0] = ffma2(pp.x, vv.x, acc[0][0]);
            acc[0][1] = ffma2(pp.x, vv.y, acc[0][1]);
            acc[1][0] = ffma2(pp.y, vv.x, acc[1][0]);
            acc[1][1] = ffma2(pp.y, vv.y, acc[1][1]);
        }
        __syncthreads();
    }

    float inv[4];
#pragma unroll
    for (int i = 0; i < 4; i++) inv[i] = 1.f / l[i];
#pragma unroll
    for (int ip = 0; ip < 2; ip++)
#pragma unroll
        for (int d = 0; d < 2; d++) {
            float2 u = up2(acc[ip][d]);
            int r0 = i0 + ty * 4 + 2 * ip;
            size_t o0 = ((size_t)b * SDIM + r0) * CS + h * DD + tx * 2 + d;
            g_att[o0] = u.x * inv[2 * ip];
            g_att[o0 + CS] = u.y * inv[2 * ip + 1];
        }
}

// ---------------- launch ----------------
extern "C" void kernel_launch(void* const* d_in, const int* in_sizes, int n_in,
                              void* d_out, int out_size) {
    const float* bs      = (const float*)d_in[0];
    const float* z       = (const float*)d_in[1];
    const float* t       = (const float*)d_in[2];
    const float* beta    = (const float*)d_in[3];
    const int*   z_mask  = (const int*)d_in[4];
    const float* w_adaln = (const float*)d_in[5];
    const float* b_adaln = (const float*)d_in[6];
    const float* ln_z_w  = (const float*)d_in[7];
    const float* ln_z_b  = (const float*)d_in[8];
    const float* w_q     = (const float*)d_in[9];
    const float* w_k     = (const float*)d_in[10];
    const float* w_v     = (const float*)d_in[11];
    const float* w_z     = (const float*)d_in[12];
    const float* rms_q_w = (const float*)d_in[13];
    const float* rms_k_w = (const float*)d_in[14];
    const float* w_o     = (const float*)d_in[15];
    const float* b_o     = (const float*)d_in[16];
    float* out = (float*)d_out;

    float *p_bsn, *p_q, *p_k, *p_v, *p_att;
    cudaGetSymbolAddress((void**)&p_bsn, g_bsn);
    cudaGetSymbolAddress((void**)&p_q,   g_q);
    cudaGetSymbolAddress((void**)&p_k,   g_k);
    cudaGetSymbolAddress((void**)&p_v,   g_v);
    cudaGetSymbolAddress((void**)&p_att, g_att);

    static bool attr_done = false;
    if (!attr_done) {
        cudaFuncSetAttribute(attn2, cudaFuncAttributeMaxDynamicSharedMemorySize, 58880);
        attr_done = true;
    }

    const int M = BDIM * SDIM;

    adaln_kernel<<<dim3(9, BDIM), 256>>>(t, w_adaln, b_adaln);
    bsnorm_kernel<<<M, 256>>>(bs);

    sgemm2<0><<<dim3(18, M / 128), 256>>>(p_bsn, w_q, w_k, w_v, p_q, p_k, p_v,
                                          rms_q_w, rms_k_w, nullptr);

    zbias_kernel<<<dim3(SDIM / 32, SDIM), 256>>>(z, ln_z_w, ln_z_b, w_z);
    cb_kernel<<<2048, 256>>>(beta, z_mask);

    attn2<<<dim3(SDIM / 64, BDIM * HN), 256, 58880>>>(p_q, p_k, p_v);

    sgemm2<1><<<dim3(6, M / 128), 256>>>(p_att, w_o, nullptr, nullptr, out, nullptr,
                                         nullptr, nullptr, nullptr, b_o);
}

// round 3
// speedup vs baseline: 1.5830x; 1.4311x over previous
#include <cuda_runtime.h>
#include <cstddef>

#define SDIM 1024
#define BDIM 2
#define CS   768
#define CZ   128
#define HN   24
#define DD   32
#define EPSF 1e-5f
#define NEGINF -1000000000.0f
#define LOG2E 1.4426950408889634f

// ---------------- scratch ----------------
__device__ float g_emb[BDIM * 3 * CS];
__device__ float g_bsn[(size_t)BDIM * SDIM * CS];
__device__ float g_q[(size_t)BDIM * SDIM * CS];
__device__ float g_k[(size_t)BDIM * SDIM * CS];
__device__ float g_v[(size_t)BDIM * SDIM * CS];
__device__ float g_zb[(size_t)HN * SDIM * SDIM];   // pre-scaled by LOG2E
__device__ float g_cb[(size_t)BDIM * SDIM * SDIM]; // pre-scaled by LOG2E
__device__ float g_att[(size_t)BDIM * SDIM * CS];
__device__ float g_w1[CZ * HN];                    // lnw[c]*wz[c,h]*LOG2E
__device__ float g_s12[2 * HN];                    // S1[h], S2[h]

// ---------------- f32x2 helpers ----------------
typedef unsigned long long u64;
__device__ __forceinline__ u64 ffma2(u64 a, u64 b, u64 c) {
    u64 d; asm("fma.rn.f32x2 %0,%1,%2,%3;" : "=l"(d) : "l"(a), "l"(b), "l"(c)); return d;
}
__device__ __forceinline__ u64 add2(u64 a, u64 b) {
    u64 d; asm("add.rn.f32x2 %0,%1,%2;" : "=l"(d) : "l"(a), "l"(b)); return d;
}
__device__ __forceinline__ u64 mul2(u64 a, u64 b) {
    u64 d; asm("mul.rn.f32x2 %0,%1,%2;" : "=l"(d) : "l"(a), "l"(b)); return d;
}
__device__ __forceinline__ u64 pk2(float a, float b) {
    u64 d; asm("mov.b64 %0,{%1,%2};" : "=l"(d) : "f"(a), "f"(b)); return d;
}
__device__ __forceinline__ float2 up2(u64 v) {
    float2 r; asm("mov.b64 {%0,%1},%2;" : "=f"(r.x), "=f"(r.y) : "l"(v)); return r;
}

// exp2 on FMA/ALU pipes (no MUFU). err ~2e-6.
__device__ __forceinline__ float exp2_fast(float x) {
    x = fmaxf(x, -125.0f);
    float r  = x + 12582912.0f;
    float fl = r - 12582912.0f;
    float f  = x - fl;
    int   n  = __float_as_int(r) - 0x4B400000;
    float p  = 1.3333558146e-3f;
    p = fmaf(p, f, 9.6181291918e-3f);
    p = fmaf(p, f, 5.5504108664e-2f);
    p = fmaf(p, f, 2.4022650696e-1f);
    p = fmaf(p, f, 6.9314718056e-1f);
    p = fmaf(p, f, 1.0f);
    return p * __int_as_float((n + 127) << 23);
}

// ---------------- 0. zbias prep ----------------
__global__ void zprep_kernel(const float* __restrict__ lnw, const float* __restrict__ lnb,
                             const float* __restrict__ wz) {
    int h = threadIdx.x;
    if (h >= HN) return;
    float s1 = 0.f, s2 = 0.f;
    for (int c = 0; c < CZ; c++) {
        float w1 = lnw[c] * wz[c * HN + h] * LOG2E;
        g_w1[c * HN + h] = w1;
        s1 += w1;
        s2 += lnb[c] * wz[c * HN + h] * LOG2E;
    }
    g_s12[h] = s1;
    g_s12[HN + h] = s2;
}

// ---------------- 1. adaLN ----------------
__global__ void adaln_kernel(const float* __restrict__ t, const float* __restrict__ w,
                             const float* __restrict__ b) {
    __shared__ float st[CS];
    int bb = blockIdx.y;
    for (int c = threadIdx.x; c < CS; c += 256) {
        float x = t[bb * CS + c];
        st[c] = x / (1.f + __expf(-x));
    }
    __syncthreads();
    int n = blockIdx.x * 256 + threadIdx.x;
    float acc = b[n];
#pragma unroll 4
    for (int c = 0; c < CS; c++) acc += st[c] * w[c * 3 * CS + n];
    g_emb[bb * 3 * CS + n] = acc;
}

// ---------------- 2. bs_norm ----------------
__global__ void bsnorm_kernel(const float* __restrict__ bs) {
    int row = blockIdx.x;
    int bb = row >> 10;
    const float* x = bs + (size_t)row * CS;
    float v[3];
    float s = 0.f, s2 = 0.f;
#pragma unroll
    for (int i = 0; i < 3; i++) {
        v[i] = x[threadIdx.x + i * 256];
        s += v[i]; s2 += v[i] * v[i];
    }
    __shared__ float rs[8], rs2[8], mvar[2];
#pragma unroll
    for (int o = 16; o; o >>= 1) {
        s  += __shfl_xor_sync(~0u, s, o);
        s2 += __shfl_xor_sync(~0u, s2, o);
    }
    int lane = threadIdx.x & 31, warp = threadIdx.x >> 5;
    if (lane == 0) { rs[warp] = s; rs2[warp] = s2; }
    __syncthreads();
    if (threadIdx.x == 0) {
        float a = 0.f, c = 0.f;
#pragma unroll
        for (int i = 0; i < 8; i++) { a += rs[i]; c += rs2[i]; }
        float mu = a * (1.f / CS);
        mvar[0] = mu;
        mvar[1] = rsqrtf(c * (1.f / CS) - mu * mu + EPSF);
    }
    __syncthreads();
    float mu = mvar[0], rstd = mvar[1];
    const float* shift = g_emb + bb * 3 * CS;
    const float* scale = shift + CS;
#pragma unroll
    for (int i = 0; i < 3; i++) {
        int c = threadIdx.x + i * 256;
        g_bsn[(size_t)row * CS + c] = (v[i] - mu) * rstd * (1.f + scale[c]) + shift[c];
    }
}

// ---------------- 3. SGEMM ----------------
template<int MODE>
__global__ __launch_bounds__(256, 2) void sgemm2(
    const float* __restrict__ A,
    const float* __restrict__ W0, const float* __restrict__ W1, const float* __restrict__ W2,
    float* __restrict__ O0, float* __restrict__ O1, float* __restrict__ O2,
    const float* __restrict__ rq, const float* __restrict__ rk,
    const float* __restrict__ bias) {
    __shared__ float As2[2][8][256];
    __shared__ float Bs[2][8][128];
    int tid = threadIdx.x, tx = tid & 15, ty = tid >> 4;
    int mat, nb;
    const float* B; float* O;
    if (MODE == 0) {
        mat = blockIdx.x / 6; nb = blockIdx.x % 6;
        B = (mat == 0) ? W0 : (mat == 1 ? W1 : W2);
        O = (mat == 0) ? O0 : (mat == 1 ? O1 : O2);
    } else { mat = 0; nb = blockIdx.x; B = W0; O = O0; }
    int m0 = blockIdx.y * 128, n0 = nb * 128;
    const int K = CS, N = CS;
    int arow = tid >> 1, acol = (tid & 1) * 4;
    int brow = tid >> 5, bcol = (tid & 31) * 4;
    const float* Ap = A + (size_t)(m0 + arow) * K + acol;
    const float* Bp = B + (size_t)brow * N + n0 + bcol;

    u64 acc[8][4];
#pragma unroll
    for (int i = 0; i < 8; i++)
#pragma unroll
        for (int j = 0; j < 4; j++) acc[i][j] = 0ULL;

    float4 a4 = *(const float4*)Ap;
    float4 b4 = *(const float4*)Bp;
    {
        float va[4] = {a4.x, a4.y, a4.z, a4.w};
#pragma unroll
        for (int w = 0; w < 4; w++)
            *(float2*)&As2[0][acol + w][2 * arow] = make_float2(va[w], va[w]);
        *(float4*)&Bs[0][brow][bcol] = b4;
    }
    __syncthreads();
    int p = 0;
    for (int kt = 8; ; kt += 8) {
        bool more = kt < K;
        if (more) {
            a4 = *(const float4*)(Ap + kt);
            b4 = *(const float4*)(Bp + (size_t)kt * N);
        }
#pragma unroll
        for (int kk = 0; kk < 8; kk++) {
            const float* ar = &As2[p][kk][ty * 16];
            ulonglong2 aA = *(const ulonglong2*)ar;
            ulonglong2 aB = *(const ulonglong2*)(ar + 4);
            ulonglong2 aC = *(const ulonglong2*)(ar + 8);
            ulonglong2 aD = *(const ulonglong2*)(ar + 12);
            const float* br = &Bs[p][kk][tx * 8];
            ulonglong2 bA = *(const ulonglong2*)br;
            ulonglong2 bB = *(const ulonglong2*)(br + 4);
            u64 av[8] = {aA.x, aA.y, aB.x, aB.y, aC.x, aC.y, aD.x, aD.y};
            u64 bv[4] = {bA.x, bA.y, bB.x, bB.y};
#pragma unroll
            for (int i = 0; i < 8; i++)
#pragma unroll
                for (int j = 0; j < 4; j++) acc[i][j] = ffma2(av[i], bv[j], acc[i][j]);
        }
        if (!more) break;
        {
            float va[4] = {a4.x, a4.y, a4.z, a4.w};
#pragma unroll
            for (int w = 0; w < 4; w++)
                *(float2*)&As2[p ^ 1][acol + w][2 * arow] = make_float2(va[w], va[w]);
            *(float4*)&Bs[p ^ 1][brow][bcol] = b4;
        }
        p ^= 1;
        __syncthreads();
    }

    float vout[8][8];
#pragma unroll
    for (int i = 0; i < 8; i++)
#pragma unroll
        for (int jp = 0; jp < 4; jp++) {
            float2 u = up2(acc[i][jp]);
            vout[i][2 * jp] = u.x; vout[i][2 * jp + 1] = u.y;
        }
    if (MODE == 0 && mat < 2) {
        const float* rw = (mat == 0) ? rq : rk;
        float w8[8];
#pragma unroll
        for (int j = 0; j < 8; j++) w8[j] = rw[(tx * 8 + j) & 31];
#pragma unroll
        for (int i = 0; i < 8; i++) {
            float ss = 0.f;
#pragma unroll
            for (int j = 0; j < 8; j++) ss += vout[i][j] * vout[i][j];
            ss += __shfl_xor_sync(~0u, ss, 1);
            ss += __shfl_xor_sync(~0u, ss, 2);
            float r = rsqrtf(ss * (1.f / DD) + EPSF);
#pragma unroll
            for (int j = 0; j < 8; j++) vout[i][j] *= r * w8[j];
        }
    }
    if (MODE == 1) {
#pragma unroll
        for (int i = 0; i < 8; i++) {
            int mrow = m0 + ty * 8 + i;
            const float* gp = g_emb + (mrow >> 10) * 3 * CS + 2 * CS;
#pragma unroll
            for (int j = 0; j < 8; j++) {
                int n = n0 + tx * 8 + j;
                vout[i][j] = (vout[i][j] + bias[n]) * gp[n];
            }
        }
    }
#pragma unroll
    for (int i = 0; i < 8; i++) {
        size_t off = (size_t)(m0 + ty * 8 + i) * N + n0 + tx * 8;
        *(float4*)&O[off]     = *(float4*)&vout[i][0];
        *(float4*)&O[off + 4] = *(float4*)&vout[i][4];
    }
}

// ---------------- 5. z bias v2: folded-LN register-blocked GEMM ----------------
#define ZJT 512
#define ZKC 8
#define ZPAD 516
__global__ __launch_bounds__(128, 3) void zbias2_kernel(const float* __restrict__ z) {
    __shared__ float zts[ZKC * ZPAD];
    __shared__ float w1s[CZ * HN];
    __shared__ float s12s[2 * HN];
    int i = blockIdx.y, j0 = blockIdx.x * ZJT;
    int t = threadIdx.x;

    {
        const float4* w1g4 = (const float4*)g_w1;
        float4* w1s4 = (float4*)w1s;
#pragma unroll
        for (int u = 0; u < 6; u++) w1s4[u * 128 + t] = w1g4[u * 128 + t];
        if (t < 2 * HN) s12s[t] = g_s12[t];
    }

    const float* zp = z + ((size_t)i * SDIM + j0) * CZ;

    u64 acc[4][12];
#pragma unroll
    for (int jj = 0; jj < 4; jj++)
#pragma unroll
        for (int hp = 0; hp < 12; hp++) acc[jj][hp] = 0ULL;
    u64 sum01 = 0ULL, sum23 = 0ULL, sq01 = 0ULL, sq23 = 0ULL;

    float4 pre[8];
#pragma unroll
    for (int l = 0; l < 8; l++) {
        int idx = l * 128 + t;
        int row = idx >> 1, half = idx & 1;
        pre[l] = *(const float4*)(zp + (size_t)row * CZ + half * 4);
    }

    for (int kt = 0; kt < CZ / ZKC; kt++) {
#pragma unroll
        for (int l = 0; l < 8; l++) {
            int idx = l * 128 + t;
            int row = idx >> 1, half = idx & 1;
            float vv[4] = {pre[l].x, pre[l].y, pre[l].z, pre[l].w};
#pragma unroll
            for (int w = 0; w < 4; w++)
                zts[(half * 4 + w) * ZPAD + row] = vv[w];
        }
        __syncthreads();
        if (kt + 1 < CZ / ZKC) {
            int c0 = (kt + 1) * ZKC;
#pragma unroll
            for (int l = 0; l < 8; l++) {
                int idx = l * 128 + t;
                int row = idx >> 1, half = idx & 1;
                pre[l] = *(const float4*)(zp + (size_t)row * CZ + c0 + half * 4);
            }
        }
#pragma unroll
        for (int c = 0; c < ZKC; c++) {
            int cg = kt * ZKC + c;
            float4 zv = *(const float4*)&zts[c * ZPAD + 4 * t];
            u64 z01 = pk2(zv.x, zv.y), z23 = pk2(zv.z, zv.w);
            sum01 = add2(sum01, z01); sum23 = add2(sum23, z23);
            sq01 = ffma2(z01, z01, sq01); sq23 = ffma2(z23, z23, sq23);
            u64 zd[4];
            zd[0] = pk2(zv.x, zv.x); zd[1] = pk2(zv.y, zv.y);
            zd[2] = pk2(zv.z, zv.z); zd[3] = pk2(zv.w, zv.w);
            const ulonglong2* wr = (const ulonglong2*)&w1s[cg * HN];
            ulonglong2 wA = wr[0], wB = wr[1], wC = wr[2];
            ulonglong2 wD = wr[3], wE = wr[4], wF = wr[5];
            u64 wp[12] = {wA.x, wA.y, wB.x, wB.y, wC.x, wC.y,
                          wD.x, wD.y, wE.x, wE.y, wF.x, wF.y};
#pragma unroll
            for (int jj = 0; jj < 4; jj++)
#pragma unroll
                for (int hp = 0; hp < 12; hp++)
                    acc[jj][hp] = ffma2(zd[jj], wp[hp], acc[jj][hp]);
        }
        __syncthreads();
    }

    float2 s01 = up2(sum01), s23 = up2(sum23);
    float2 q01 = up2(sq01), q23 = up2(sq23);
    float S[4] = {s01.x, s01.y, s23.x, s23.y};
    float Q[4] = {q01.x, q01.y, q23.x, q23.y};
    float mu[4], rstd[4];
#pragma unroll
    for (int jj = 0; jj < 4; jj++) {
        mu[jj] = S[jj] * (1.f / CZ);
        rstd[jj] = rsqrtf(Q[jj] * (1.f / CZ) - mu[jj] * mu[jj] + EPSF);
    }
#pragma unroll
    for (int hp = 0; hp < 12; hp++) {
        float s1a = s12s[2 * hp], s1b = s12s[2 * hp + 1];
        float s2a = s12s[HN + 2 * hp], s2b = s12s[HN + 2 * hp + 1];
        float oa[4], ob[4];
#pragma unroll
        for (int jj = 0; jj < 4; jj++) {
            float2 a = up2(acc[jj][hp]);
            oa[jj] = rstd[jj] * (a.x - mu[jj] * s1a) + s2a;
            ob[jj] = rstd[jj] * (a.y - mu[jj] * s1b) + s2b;
        }
        size_t base_a = (((size_t)(2 * hp) * SDIM + i) * SDIM) + j0 + 4 * t;
        size_t base_b = (((size_t)(2 * hp + 1) * SDIM + i) * SDIM) + j0 + 4 * t;
        *(float4*)&g_zb[base_a] = make_float4(oa[0], oa[1], oa[2], oa[3]);
        *(float4*)&g_zb[base_b] = make_float4(ob[0], ob[1], ob[2], ob[3]);
    }
}

// ---------------- 6. combined bias ----------------
__global__ void cb_kernel(const float* __restrict__ beta, const int* __restrict__ mask) {
    size_t total = (size_t)BDIM * SDIM * SDIM;
    for (size_t idx = (size_t)blockIdx.x * 256 + threadIdx.x; idx < total;
         idx += (size_t)gridDim.x * 256) {
        size_t ij = idx & ((size_t)SDIM * SDIM - 1);
        g_cb[idx] = (beta[idx] + (mask[ij] > 0 ? 0.f : NEGINF)) * LOG2E;
    }
}

// ---------------- 7. flash attention ----------------
__global__ __launch_bounds__(256, 2) void attn2(const float* __restrict__ q,
                                                const float* __restrict__ k,
                                                const float* __restrict__ v) {
    extern __shared__ float sm[];
    float* QT2 = sm;
    float* KT  = sm + 4096;
    float* VS2 = sm + 6272;
    float* PT  = sm + 10368;
    int bh = blockIdx.y, b = bh / HN, h = bh - b * HN;
    int i0 = blockIdx.x * 64;
    int tid = threadIdx.x, tx = tid & 15, ty = tid >> 4;
    const float sc = 0.17677669529663687f * LOG2E;

    const float* qp = q + (size_t)b * SDIM * CS + h * DD;
    const float* kp = k + (size_t)b * SDIM * CS + h * DD;
    const float* vp = v + (size_t)b * SDIM * CS + h * DD;
    const float* zbp = g_zb + (size_t)h * SDIM * SDIM;
    const float* cbp = g_cb + (size_t)b * SDIM * SDIM;

    for (int u = tid; u < 512; u += 256) {
        int r = u >> 3, c4 = u & 7;
        float4 t4 = *(const float4*)(qp + (size_t)(i0 + r) * CS + c4 * 4);
        int d0 = c4 * 4;
        *(float2*)&QT2[(d0 + 0) * 128 + 2 * r] = make_float2(t4.x * sc, t4.x * sc);
        *(float2*)&QT2[(d0 + 1) * 128 + 2 * r] = make_float2(t4.y * sc, t4.y * sc);
        *(float2*)&QT2[(d0 + 2) * 128 + 2 * r] = make_float2(t4.z * sc, t4.z * sc);
        *(float2*)&QT2[(d0 + 3) * 128 + 2 * r] = make_float2(t4.w * sc, t4.w * sc);
    }

    u64 acc[2][2] = {0ULL, 0ULL, 0ULL, 0ULL};
    float m[4], l[4];
#pragma unroll
    for (int i = 0; i < 4; i++) { m[i] = -1e30f; l[i] = 0.f; }

    for (int j0 = 0; j0 < SDIM; j0 += 64) {
        for (int u = tid; u < 512; u += 256) {
            int r = u >> 3, c4 = u & 7;
            float4 kv = *(const float4*)(kp + (size_t)(j0 + r) * CS + c4 * 4);
            KT[(c4 * 4 + 0) * 68 + r] = kv.x;
            KT[(c4 * 4 + 1) * 68 + r] = kv.y;
            KT[(c4 * 4 + 2) * 68 + r] = kv.z;
            KT[(c4 * 4 + 3) * 68 + r] = kv.w;
            float4 vv = *(const float4*)(vp + (size_t)(j0 + r) * CS + c4 * 4);
            *(float2*)&VS2[r * 64 + (c4 * 4 + 0) * 2] = make_float2(vv.x, vv.x);
            *(float2*)&VS2[r * 64 + (c4 * 4 + 1) * 2] = make_float2(vv.y, vv.y);
            *(float2*)&VS2[r * 64 + (c4 * 4 + 2) * 2] = make_float2(vv.z, vv.z);
            *(float2*)&VS2[r * 64 + (c4 * 4 + 3) * 2] = make_float2(vv.w, vv.w);
        }
        u64 s[4][2];
#pragma unroll
        for (int i = 0; i < 4; i++) {
            size_t ro = (size_t)(i0 + ty * 4 + i) * SDIM + j0 + tx * 4;
            ulonglong2 zb2 = *(const ulonglong2*)(zbp + ro);
            ulonglong2 cb2 = *(const ulonglong2*)(cbp + ro);
            s[i][0] = add2(zb2.x, cb2.x);
            s[i][1] = add2(zb2.y, cb2.y);
        }
        __syncthreads();

#pragma unroll 8
        for (int kk = 0; kk < DD; kk++) {
            const float* ar = &QT2[kk * 128 + ty * 8];
            ulonglong2 aA = *(const ulonglong2*)ar;
            ulonglong2 aB = *(const ulonglong2*)(ar + 4);
            ulonglong2 bA = *(const ulonglong2*)&KT[kk * 68 + tx * 4];
            s[0][0] = ffma2(aA.x, bA.x, s[0][0]); s[0][1] = ffma2(aA.x, bA.y, s[0][1]);
            s[1][0] = ffma2(aA.y, bA.x, s[1][0]); s[1][1] = ffma2(aA.y, bA.y, s[1][1]);
            s[2][0] = ffma2(aB.x, bA.x, s[2][0]); s[2][1] = ffma2(aB.x, bA.y, s[2][1]);
            s[3][0] = ffma2(aB.y, bA.x, s[3][0]); s[3][1] = ffma2(aB.y, bA.y, s[3][1]);
        }

        float corr[4];
#pragma unroll
        for (int i = 0; i < 4; i++) {
            float2 p0 = up2(s[i][0]), p1 = up2(s[i][1]);
            float mx = fmaxf(fmaxf(p0.x, p0.y), fmaxf(p1.x, p1.y));
#pragma unroll
            for (int o = 8; o; o >>= 1) mx = fmaxf(mx, __shfl_xor_sync(~0u, mx, o));
            float mn = fmaxf(m[i], mx);
            corr[i] = exp2_fast(m[i] - mn);
            m[i] = mn;
            float e0 = exp2_fast(p0.x - mn), e1 = exp2_fast(p0.y - mn);
            float e2 = exp2_fast(p1.x - mn), e3 = exp2_fast(p1.y - mn);
            float ls = e0 + e1 + e2 + e3;
#pragma unroll
            for (int o = 8; o; o >>= 1) ls += __shfl_xor_sync(~0u, ls, o);
            l[i] = l[i] * corr[i] + ls;
            int col = ty * 4 + i;
            PT[(tx * 4 + 0) * 68 + col] = e0;
            PT[(tx * 4 + 1) * 68 + col] = e1;
            PT[(tx * 4 + 2) * 68 + col] = e2;
            PT[(tx * 4 + 3) * 68 + col] = e3;
        }
        {
            u64 c01 = pk2(corr[0], corr[1]);
            u64 c23 = pk2(corr[2], corr[3]);
            acc[0][0] = mul2(acc[0][0], c01); acc[0][1] = mul2(acc[0][1], c01);
            acc[1][0] = mul2(acc[1][0], c23); acc[1][1] = mul2(acc[1][1], c23);
        }
        __syncthreads();

#pragma unroll 8
        for (int kk = 0; kk < 64; kk++) {
            ulonglong2 pp = *(const ulonglong2*)&PT[kk * 68 + ty * 4];
            ulonglong2 vv = *(const ulonglong2*)&VS2[kk * 64 + tx * 4];
            acc[0][0] = ffma2(pp.x, vv.x, acc[0][0]);
            acc[0][1] = ffma2(pp.x, vv.y, acc[0][1]);
            acc[1][0] = ffma2(pp.y, vv.x, acc[1][0]);
            acc[1][1] = ffma2(pp.y, vv.y, acc[1][1]);
        }
        __syncthreads();
    }

    float inv[4];
#pragma unroll
    for (int i = 0; i < 4; i++) inv[i] = 1.f / l[i];
#pragma unroll
    for (int ip = 0; ip < 2; ip++)
#pragma unroll
        for (int d = 0; d < 2; d++) {
            float2 u = up2(acc[ip][d]);
            int r0 = i0 + ty * 4 + 2 * ip;
            size_t o0 = ((size_t)b * SDIM + r0) * CS + h * DD + tx * 2 + d;
            g_att[o0] = u.x * inv[2 * ip];
            g_att[o0 + CS] = u.y * inv[2 * ip + 1];
        }
}

// ---------------- launch ----------------
extern "C" void kernel_launch(void* const* d_in, const int* in_sizes, int n_in,
                              void* d_out, int out_size) {
    const float* bs      = (const float*)d_in[0];
    const float* z       = (const float*)d_in[1];
    const float* t       = (const float*)d_in[2];
    const float* beta    = (const float*)d_in[3];
    const int*   z_mask  = (const int*)d_in[4];
    const float* w_adaln = (const float*)d_in[5];
    const float* b_adaln = (const float*)d_in[6];
    const float* ln_z_w  = (const float*)d_in[7];
    const float* ln_z_b  = (const float*)d_in[8];
    const float* w_q     = (const float*)d_in[9];
    const float* w_k     = (const float*)d_in[10];
    const float* w_v     = (const float*)d_in[11];
    const float* w_z     = (const float*)d_in[12];
    const float* rms_q_w = (const float*)d_in[13];
    const float* rms_k_w = (const float*)d_in[14];
    const float* w_o     = (const float*)d_in[15];
    const float* b_o     = (const float*)d_in[16];
    float* out = (float*)d_out;

    float *p_bsn, *p_q, *p_k, *p_v, *p_att;
    cudaGetSymbolAddress((void**)&p_bsn, g_bsn);
    cudaGetSymbolAddress((void**)&p_q,   g_q);
    cudaGetSymbolAddress((void**)&p_k,   g_k);
    cudaGetSymbolAddress((void**)&p_v,   g_v);
    cudaGetSymbolAddress((void**)&p_att, g_att);

    static bool attr_done = false;
    if (!attr_done) {
        cudaFuncSetAttribute(attn2, cudaFuncAttributeMaxDynamicSharedMemorySize, 58880);
        attr_done = true;
    }

    const int M = BDIM * SDIM;

    zprep_kernel<<<1, 32>>>(ln_z_w, ln_z_b, w_z);
    adaln_kernel<<<dim3(9, BDIM), 256>>>(t, w_adaln, b_adaln);
    bsnorm_kernel<<<M, 256>>>(bs);

    sgemm2<0><<<dim3(18, M / 128), 256>>>(p_bsn, w_q, w_k, w_v, p_q, p_k, p_v,
                                          rms_q_w, rms_k_w, nullptr);

    zbias2_kernel<<<dim3(SDIM / ZJT, SDIM), 128>>>(z);
    cb_kernel<<<2048, 256>>>(beta, z_mask);

    attn2<<<dim3(SDIM / 64, BDIM * HN), 256, 58880>>>(p_q, p_k, p_v);

    sgemm2<1><<<dim3(6, M / 128), 256>>>(p_att, w_o, nullptr, nullptr, out, nullptr,
                                         nullptr, nullptr, nullptr, b_o);
}

// round 5
// speedup vs baseline: 1.6619x; 1.0498x over previous
#include <cuda_runtime.h>
#include <cstddef>

#define SDIM 1024
#define BDIM 2
#define CS   768
#define CZ   128
#define HN   24
#define DD   32
#define EPSF 1e-5f
#define NEGINF -1000000000.0f
#define LOG2E 1.4426950408889634f

// ---------------- scratch ----------------
__device__ float g_emb[BDIM * 3 * CS];
__device__ float g_bsn[(size_t)BDIM * SDIM * CS];
__device__ float g_q[(size_t)BDIM * SDIM * CS];
__device__ float g_k[(size_t)BDIM * SDIM * CS];
__device__ float g_v[(size_t)BDIM * SDIM * CS];
__device__ float g_zb[(size_t)HN * SDIM * SDIM];   // pre-scaled by LOG2E
__device__ float g_cb[(size_t)BDIM * SDIM * SDIM]; // pre-scaled by LOG2E
__device__ float g_att[(size_t)BDIM * SDIM * CS];
__device__ float g_w1[CZ * HN];                    // lnw[c]*wz[c,h]*LOG2E
__device__ float g_s12[2 * HN];                    // S1[h], S2[h]

// ---------------- f32x2 helpers ----------------
typedef unsigned long long u64;
__device__ __forceinline__ u64 ffma2(u64 a, u64 b, u64 c) {
    u64 d; asm("fma.rn.f32x2 %0,%1,%2,%3;" : "=l"(d) : "l"(a), "l"(b), "l"(c)); return d;
}
__device__ __forceinline__ u64 add2(u64 a, u64 b) {
    u64 d; asm("add.rn.f32x2 %0,%1,%2;" : "=l"(d) : "l"(a), "l"(b)); return d;
}
__device__ __forceinline__ u64 pk2(float a, float b) {
    u64 d; asm("mov.b64 %0,{%1,%2};" : "=l"(d) : "f"(a), "f"(b)); return d;
}
__device__ __forceinline__ float2 up2(u64 v) {
    float2 r; asm("mov.b64 {%0,%1},%2;" : "=f"(r.x), "=f"(r.y) : "l"(v)); return r;
}
// MUFU exp2: ex2.approx.f32 (large-negative -> +0)
__device__ __forceinline__ float ex2(float x) {
    float y; asm("ex2.approx.f32 %0, %1;" : "=f"(y) : "f"(x)); return y;
}

// ---------------- 0. zbias prep ----------------
__global__ void zprep_kernel(const float* __restrict__ lnw, const float* __restrict__ lnb,
                             const float* __restrict__ wz) {
    int h = threadIdx.x;
    if (h >= HN) return;
    float s1 = 0.f, s2 = 0.f;
    for (int c = 0; c < CZ; c++) {
        float w1 = lnw[c] * wz[c * HN + h] * LOG2E;
        g_w1[c * HN + h] = w1;
        s1 += w1;
        s2 += lnb[c] * wz[c * HN + h] * LOG2E;
    }
    g_s12[h] = s1;
    g_s12[HN + h] = s2;
}

// ---------------- 1. adaLN ----------------
__global__ void adaln_kernel(const float* __restrict__ t, const float* __restrict__ w,
                             const float* __restrict__ b) {
    __shared__ float st[CS];
    int bb = blockIdx.y;
    for (int c = threadIdx.x; c < CS; c += 256) {
        float x = t[bb * CS + c];
        st[c] = x / (1.f + __expf(-x));
    }
    __syncthreads();
    int n = blockIdx.x * 256 + threadIdx.x;
    float acc = b[n];
#pragma unroll 4
    for (int c = 0; c < CS; c++) acc += st[c] * w[c * 3 * CS + n];
    g_emb[bb * 3 * CS + n] = acc;
}

// ---------------- 2. bs_norm ----------------
__global__ void bsnorm_kernel(const float* __restrict__ bs) {
    int row = blockIdx.x;
    int bb = row >> 10;
    const float* x = bs + (size_t)row * CS;
    float v[3];
    float s = 0.f, s2 = 0.f;
#pragma unroll
    for (int i = 0; i < 3; i++) {
        v[i] = x[threadIdx.x + i * 256];
        s += v[i]; s2 += v[i] * v[i];
    }
    __shared__ float rs[8], rs2[8], mvar[2];
#pragma unroll
    for (int o = 16; o; o >>= 1) {
        s  += __shfl_xor_sync(~0u, s, o);
        s2 += __shfl_xor_sync(~0u, s2, o);
    }
    int lane = threadIdx.x & 31, warp = threadIdx.x >> 5;
    if (lane == 0) { rs[warp] = s; rs2[warp] = s2; }
    __syncthreads();
    if (threadIdx.x == 0) {
        float a = 0.f, c = 0.f;
#pragma unroll
        for (int i = 0; i < 8; i++) { a += rs[i]; c += rs2[i]; }
        float mu = a * (1.f / CS);
        mvar[0] = mu;
        mvar[1] = rsqrtf(c * (1.f / CS) - mu * mu + EPSF);
    }
    __syncthreads();
    float mu = mvar[0], rstd = mvar[1];
    const float* shift = g_emb + bb * 3 * CS;
    const float* scale = shift + CS;
#pragma unroll
    for (int i = 0; i < 3; i++) {
        int c = threadIdx.x + i * 256;
        g_bsn[(size_t)row * CS + c] = (v[i] - mu) * rstd * (1.f + scale[c]) + shift[c];
    }
}

// ---------------- 3. SGEMM ----------------
template<int MODE>
__global__ __launch_bounds__(256, 2) void sgemm2(
    const float* __restrict__ A,
    const float* __restrict__ W0, const float* __restrict__ W1, const float* __restrict__ W2,
    float* __restrict__ O0, float* __restrict__ O1, float* __restrict__ O2,
    const float* __restrict__ rq, const float* __restrict__ rk,
    const float* __restrict__ bias) {
    __shared__ float As2[2][8][256];
    __shared__ float Bs[2][8][128];
    int tid = threadIdx.x, tx = tid & 15, ty = tid >> 4;
    int mat, nb;
    const float* B; float* O;
    if (MODE == 0) {
        mat = blockIdx.x / 6; nb = blockIdx.x % 6;
        B = (mat == 0) ? W0 : (mat == 1 ? W1 : W2);
        O = (mat == 0) ? O0 : (mat == 1 ? O1 : O2);
    } else { mat = 0; nb = blockIdx.x; B = W0; O = O0; }
    int m0 = blockIdx.y * 128, n0 = nb * 128;
    const int K = CS, N = CS;
    int arow = tid >> 1, acol = (tid & 1) * 4;
    int brow = tid >> 5, bcol = (tid & 31) * 4;
    const float* Ap = A + (size_t)(m0 + arow) * K + acol;
    const float* Bp = B + (size_t)brow * N + n0 + bcol;

    u64 acc[8][4];
#pragma unroll
    for (int i = 0; i < 8; i++)
#pragma unroll
        for (int j = 0; j < 4; j++) acc[i][j] = 0ULL;

    float4 a4 = *(const float4*)Ap;
    float4 b4 = *(const float4*)Bp;
    {
        float va[4] = {a4.x, a4.y, a4.z, a4.w};
#pragma unroll
        for (int w = 0; w < 4; w++)
            *(float2*)&As2[0][acol + w][2 * arow] = make_float2(va[w], va[w]);
        *(float4*)&Bs[0][brow][bcol] = b4;
    }
    __syncthreads();
    int p = 0;
    for (int kt = 8; ; kt += 8) {
        bool more = kt < K;
        if (more) {
            a4 = *(const float4*)(Ap + kt);
            b4 = *(const float4*)(Bp + (size_t)kt * N);
        }
#pragma unroll
        for (int kk = 0; kk < 8; kk++) {
            const float* ar = &As2[p][kk][ty * 16];
            ulonglong2 aA = *(const ulonglong2*)ar;
            ulonglong2 aB = *(const ulonglong2*)(ar + 4);
            ulonglong2 aC = *(const ulonglong2*)(ar + 8);
            ulonglong2 aD = *(const ulonglong2*)(ar + 12);
            const float* br = &Bs[p][kk][tx * 8];
            ulonglong2 bA = *(const ulonglong2*)br;
            ulonglong2 bB = *(const ulonglong2*)(br + 4);
            u64 av[8] = {aA.x, aA.y, aB.x, aB.y, aC.x, aC.y, aD.x, aD.y};
            u64 bv[4] = {bA.x, bA.y, bB.x, bB.y};
#pragma unroll
            for (int i = 0; i < 8; i++)
#pragma unroll
                for (int j = 0; j < 4; j++) acc[i][j] = ffma2(av[i], bv[j], acc[i][j]);
        }
        if (!more) break;
        {
            float va[4] = {a4.x, a4.y, a4.z, a4.w};
#pragma unroll
            for (int w = 0; w < 4; w++)
                *(float2*)&As2[p ^ 1][acol + w][2 * arow] = make_float2(va[w], va[w]);
            *(float4*)&Bs[p ^ 1][brow][bcol] = b4;
        }
        p ^= 1;
        __syncthreads();
    }

    float vout[8][8];
#pragma unroll
    for (int i = 0; i < 8; i++)
#pragma unroll
        for (int jp = 0; jp < 4; jp++) {
            float2 u = up2(acc[i][jp]);
            vout[i][2 * jp] = u.x; vout[i][2 * jp + 1] = u.y;
        }
    if (MODE == 0 && mat < 2) {
        const float* rw = (mat == 0) ? rq : rk;
        float w8[8];
#pragma unroll
        for (int j = 0; j < 8; j++) w8[j] = rw[(tx * 8 + j) & 31];
#pragma unroll
        for (int i = 0; i < 8; i++) {
            float ss = 0.f;
#pragma unroll
            for (int j = 0; j < 8; j++) ss += vout[i][j] * vout[i][j];
            ss += __shfl_xor_sync(~0u, ss, 1);
            ss += __shfl_xor_sync(~0u, ss, 2);
            float r = rsqrtf(ss * (1.f / DD) + EPSF);
#pragma unroll
            for (int j = 0; j < 8; j++) vout[i][j] *= r * w8[j];
        }
    }
    if (MODE == 1) {
#pragma unroll
        for (int i = 0; i < 8; i++) {
            int mrow = m0 + ty * 8 + i;
            const float* gp = g_emb + (mrow >> 10) * 3 * CS + 2 * CS;
#pragma unroll
            for (int j = 0; j < 8; j++) {
                int n = n0 + tx * 8 + j;
                vout[i][j] = (vout[i][j] + bias[n]) * gp[n];
            }
        }
    }
#pragma unroll
    for (int i = 0; i < 8; i++) {
        size_t off = (size_t)(m0 + ty * 8 + i) * N + n0 + tx * 8;
        *(float4*)&O[off]     = *(float4*)&vout[i][0];
        *(float4*)&O[off + 4] = *(float4*)&vout[i][4];
    }
}

// ---------------- 5. z bias v2 ----------------
#define ZJT 512
#define ZKC 8
#define ZPAD 516
__global__ __launch_bounds__(128, 3) void zbias2_kernel(const float* __restrict__ z) {
    __shared__ float zts[ZKC * ZPAD];
    __shared__ float w1s[CZ * HN];
    __shared__ float s12s[2 * HN];
    int i = blockIdx.y, j0 = blockIdx.x * ZJT;
    int t = threadIdx.x;

    {
        const float4* w1g4 = (const float4*)g_w1;
        float4* w1s4 = (float4*)w1s;
#pragma unroll
        for (int u = 0; u < 6; u++) w1s4[u * 128 + t] = w1g4[u * 128 + t];
        if (t < 2 * HN) s12s[t] = g_s12[t];
    }

    const float* zp = z + ((size_t)i * SDIM + j0) * CZ;

    u64 acc[4][12];
#pragma unroll
    for (int jj = 0; jj < 4; jj++)
#pragma unroll
        for (int hp = 0; hp < 12; hp++) acc[jj][hp] = 0ULL;
    u64 sum01 = 0ULL, sum23 = 0ULL, sq01 = 0ULL, sq23 = 0ULL;

    float4 pre[8];
#pragma unroll
    for (int l = 0; l < 8; l++) {
        int idx = l * 128 + t;
        int row = idx >> 1, half = idx & 1;
        pre[l] = *(const float4*)(zp + (size_t)row * CZ + half * 4);
    }

    for (int kt = 0; kt < CZ / ZKC; kt++) {
#pragma unroll
        for (int l = 0; l < 8; l++) {
            int idx = l * 128 + t;
            int row = idx >> 1, half = idx & 1;
            float vv[4] = {pre[l].x, pre[l].y, pre[l].z, pre[l].w};
#pragma unroll
            for (int w = 0; w < 4; w++)
                zts[(half * 4 + w) * ZPAD + row] = vv[w];
        }
        __syncthreads();
        if (kt + 1 < CZ / ZKC) {
            int c0 = (kt + 1) * ZKC;
#pragma unroll
            for (int l = 0; l < 8; l++) {
                int idx = l * 128 + t;
                int row = idx >> 1, half = idx & 1;
                pre[l] = *(const float4*)(zp + (size_t)row * CZ + c0 + half * 4);
            }
        }
#pragma unroll
        for (int c = 0; c < ZKC; c++) {
            int cg = kt * ZKC + c;
            float4 zv = *(const float4*)&zts[c * ZPAD + 4 * t];
            u64 z01 = pk2(zv.x, zv.y), z23 = pk2(zv.z, zv.w);
            sum01 = add2(sum01, z01); sum23 = add2(sum23, z23);
            sq01 = ffma2(z01, z01, sq01); sq23 = ffma2(z23, z23, sq23);
            u64 zd[4];
            zd[0] = pk2(zv.x, zv.x); zd[1] = pk2(zv.y, zv.y);
            zd[2] = pk2(zv.z, zv.z); zd[3] = pk2(zv.w, zv.w);
            const ulonglong2* wr = (const ulonglong2*)&w1s[cg * HN];
            ulonglong2 wA = wr[0], wB = wr[1], wC = wr[2];
            ulonglong2 wD = wr[3], wE = wr[4], wF = wr[5];
            u64 wp[12] = {wA.x, wA.y, wB.x, wB.y, wC.x, wC.y,
                          wD.x, wD.y, wE.x, wE.y, wF.x, wF.y};
#pragma unroll
            for (int jj = 0; jj < 4; jj++)
#pragma unroll
                for (int hp = 0; hp < 12; hp++)
                    acc[jj][hp] = ffma2(zd[jj], wp[hp], acc[jj][hp]);
        }
        __syncthreads();
    }

    float2 s01 = up2(sum01), s23 = up2(sum23);
    float2 q01 = up2(sq01), q23 = up2(sq23);
    float S[4] = {s01.x, s01.y, s23.x, s23.y};
    float Q[4] = {q01.x, q01.y, q23.x, q23.y};
    float mu[4], rstd[4];
#pragma unroll
    for (int jj = 0; jj < 4; jj++) {
        mu[jj] = S[jj] * (1.f / CZ);
        rstd[jj] = rsqrtf(Q[jj] * (1.f / CZ) - mu[jj] * mu[jj] + EPSF);
    }
#pragma unroll
    for (int hp = 0; hp < 12; hp++) {
        float s1a = s12s[2 * hp], s1b = s12s[2 * hp + 1];
        float s2a = s12s[HN + 2 * hp], s2b = s12s[HN + 2 * hp + 1];
        float oa[4], ob[4];
#pragma unroll
        for (int jj = 0; jj < 4; jj++) {
            float2 a = up2(acc[jj][hp]);
            oa[jj] = rstd[jj] * (a.x - mu[jj] * s1a) + s2a;
            ob[jj] = rstd[jj] * (a.y - mu[jj] * s1b) + s2b;
        }
        size_t base_a = (((size_t)(2 * hp) * SDIM + i) * SDIM) + j0 + 4 * t;
        size_t base_b = (((size_t)(2 * hp + 1) * SDIM + i) * SDIM) + j0 + 4 * t;
        *(float4*)&g_zb[base_a] = make_float4(oa[0], oa[1], oa[2], oa[3]);
        *(float4*)&g_zb[base_b] = make_float4(ob[0], ob[1], ob[2], ob[3]);
    }
}

// ---------------- 6. combined bias ----------------
__global__ void cb_kernel(const float* __restrict__ beta, const int* __restrict__ mask) {
    size_t total = (size_t)BDIM * SDIM * SDIM;
    for (size_t idx = (size_t)blockIdx.x * 256 + threadIdx.x; idx < total;
         idx += (size_t)gridDim.x * 256) {
        size_t ij = idx & ((size_t)SDIM * SDIM - 1);
        g_cb[idx] = (beta[idx] + (mask[ij] > 0 ? 0.f : NEGINF)) * LOG2E;
    }
}

// ---------------- 7. flash attention v3: no-max softmax, MUFU exp2 ----------------
// Valid because q,k are RMS-normalized: |score| <= sqrt(32)+|beta|+|zbias| < 12,
// so exp2 never overflows without max subtraction. Masked: ex2(-1.4e9) = 0.
__global__ __launch_bounds__(256, 3) void attn3(const float* __restrict__ q,
                                                const float* __restrict__ k,
                                                const float* __restrict__ v) {
    extern __shared__ float sm[];
    float* QT2 = sm;            // [32][128]  dup'd transposed Q * sc
    float* KT  = sm + 4096;     // [32][68]   transposed K
    float* VS2 = sm + 6272;     // [64][64]   dup'd V
    float* PT  = sm + 10368;    // [64][68]   transposed P
    int bh = blockIdx.y, b = bh / HN, h = bh - b * HN;
    int i0 = blockIdx.x * 64;
    int tid = threadIdx.x, tx = tid & 15, ty = tid >> 4;
    const float sc = 0.17677669529663687f * LOG2E;

    const float* qp = q + (size_t)b * SDIM * CS + h * DD;
    const float* kp = k + (size_t)b * SDIM * CS + h * DD;
    const float* vp = v + (size_t)b * SDIM * CS + h * DD;
    const float* zbp = g_zb + (size_t)h * SDIM * SDIM;
    const float* cbp = g_cb + (size_t)b * SDIM * SDIM;

    for (int u = tid; u < 512; u += 256) {
        int r = u >> 3, c4 = u & 7;
        float4 t4 = *(const float4*)(qp + (size_t)(i0 + r) * CS + c4 * 4);
        int d0 = c4 * 4;
        *(float2*)&QT2[(d0 + 0) * 128 + 2 * r] = make_float2(t4.x * sc, t4.x * sc);
        *(float2*)&QT2[(d0 + 1) * 128 + 2 * r] = make_float2(t4.y * sc, t4.y * sc);
        *(float2*)&QT2[(d0 + 2) * 128 + 2 * r] = make_float2(t4.z * sc, t4.z * sc);
        *(float2*)&QT2[(d0 + 3) * 128 + 2 * r] = make_float2(t4.w * sc, t4.w * sc);
    }

    u64 acc[2][2] = {0ULL, 0ULL, 0ULL, 0ULL};
    float lp[4] = {0.f, 0.f, 0.f, 0.f};

    for (int j0 = 0; j0 < SDIM; j0 += 64) {
        for (int u = tid; u < 512; u += 256) {
            int r = u >> 3, c4 = u & 7;
            float4 kv = *(const float4*)(kp + (size_t)(j0 + r) * CS + c4 * 4);
            KT[(c4 * 4 + 0) * 68 + r] = kv.x;
            KT[(c4 * 4 + 1) * 68 + r] = kv.y;
            KT[(c4 * 4 + 2) * 68 + r] = kv.z;
            KT[(c4 * 4 + 3) * 68 + r] = kv.w;
            float4 vv = *(const float4*)(vp + (size_t)(j0 + r) * CS + c4 * 4);
            *(float2*)&VS2[r * 64 + (c4 * 4 + 0) * 2] = make_float2(vv.x, vv.x);
            *(float2*)&VS2[r * 64 + (c4 * 4 + 1) * 2] = make_float2(vv.y, vv.y);
            *(float2*)&VS2[r * 64 + (c4 * 4 + 2) * 2] = make_float2(vv.z, vv.z);
            *(float2*)&VS2[r * 64 + (c4 * 4 + 3) * 2] = make_float2(vv.w, vv.w);
        }
        u64 s[4][2];
#pragma unroll
        for (int i = 0; i < 4; i++) {
            size_t ro = (size_t)(i0 + ty * 4 + i) * SDIM + j0 + tx * 4;
            ulonglong2 zb2 = *(const ulonglong2*)(zbp + ro);
            ulonglong2 cb2 = *(const ulonglong2*)(cbp + ro);
            s[i][0] = add2(zb2.x, cb2.x);
            s[i][1] = add2(zb2.y, cb2.y);
        }
        __syncthreads();

#pragma unroll 8
        for (int kk = 0; kk < DD; kk++) {
            const float* ar = &QT2[kk * 128 + ty * 8];
            ulonglong2 aA = *(const ulonglong2*)ar;
            ulonglong2 aB = *(const ulonglong2*)(ar + 4);
            ulonglong2 bA = *(const ulonglong2*)&KT[kk * 68 + tx * 4];
            s[0][0] = ffma2(aA.x, bA.x, s[0][0]); s[0][1] = ffma2(aA.x, bA.y, s[0][1]);
            s[1][0] = ffma2(aA.y, bA.x, s[1][0]); s[1][1] = ffma2(aA.y, bA.y, s[1][1]);
            s[2][0] = ffma2(aB.x, bA.x, s[2][0]); s[2][1] = ffma2(aB.x, bA.y, s[2][1]);
            s[3][0] = ffma2(aB.y, bA.x, s[3][0]); s[3][1] = ffma2(aB.y, bA.y, s[3][1]);
        }

        // softmax numerator: p = exp2(s), no max needed; accumulate partial row sums
#pragma unroll
        for (int i = 0; i < 4; i++) {
            float2 p0 = up2(s[i][0]), p1 = up2(s[i][1]);
            float e0 = ex2(p0.x), e1 = ex2(p0.y);
            float e2 = ex2(p1.x), e3 = ex2(p1.y);
            lp[i] += (e0 + e1) + (e2 + e3);
            int col = ty * 4 + i;
            PT[(tx * 4 + 0) * 68 + col] = e0;
            PT[(tx * 4 + 1) * 68 + col] = e1;
            PT[(tx * 4 + 2) * 68 + col] = e2;
            PT[(tx * 4 + 3) * 68 + col] = e3;
        }
        __syncthreads();

#pragma unroll 8
        for (int kk = 0; kk < 64; kk++) {
            ulonglong2 pp = *(const ulonglong2*)&PT[kk * 68 + ty * 4];
            ulonglong2 vv = *(const ulonglong2*)&VS2[kk * 64 + tx * 4];
            acc[0][0] = ffma2(pp.x, vv.x, acc[0][0]);
            acc[0][1] = ffma2(pp.x, vv.y, acc[0][1]);
            acc[1][0] = ffma2(pp.y, vv.x, acc[1][0]);
            acc[1][1] = ffma2(pp.y, vv.y, acc[1][1]);
        }
        __syncthreads();
    }

    // final row-sum reduction across the 16 tx lanes (offsets 1,2,4,8 stay in-warp)
#pragma unroll
    for (int i = 0; i < 4; i++) {
#pragma unroll
        for (int o = 8; o; o >>= 1) lp[i] += __shfl_xor_sync(~0u, lp[i], o);
    }
    float inv[4];
#pragma unroll
    for (int i = 0; i < 4; i++) inv[i] = 1.f / lp[i];
#pragma unroll
    for (int ip = 0; ip < 2; ip++)
#pragma unroll
        for (int d = 0; d < 2; d++) {
            float2 u = up2(acc[ip][d]);
            int r0 = i0 + ty * 4 + 2 * ip;
            size_t o0 = ((size_t)b * SDIM + r0) * CS + h * DD + tx * 2 + d;
            g_att[o0] = u.x * inv[2 * ip];
            g_att[o0 + CS] = u.y * inv[2 * ip + 1];
        }
}

// ---------------- launch ----------------
extern "C" void kernel_launch(void* const* d_in, const int* in_sizes, int n_in,
                              void* d_out, int out_size) {
    const float* bs      = (const float*)d_in[0];
    const float* z       = (const float*)d_in[1];
    const float* t       = (const float*)d_in[2];
    const float* beta    = (const float*)d_in[3];
    const int*   z_mask  = (const int*)d_in[4];
    const float* w_adaln = (const float*)d_in[5];
    const float* b_adaln = (const float*)d_in[6];
    const float* ln_z_w  = (const float*)d_in[7];
    const float* ln_z_b  = (const float*)d_in[8];
    const float* w_q     = (const float*)d_in[9];
    const float* w_k     = (const float*)d_in[10];
    const float* w_v     = (const float*)d_in[11];
    const float* w_z     = (const float*)d_in[12];
    const float* rms_q_w = (const float*)d_in[13];
    const float* rms_k_w = (const float*)d_in[14];
    const float* w_o     = (const float*)d_in[15];
    const float* b_o     = (const float*)d_in[16];
    float* out = (float*)d_out;

    float *p_bsn, *p_q, *p_k, *p_v, *p_att;
    cudaGetSymbolAddress((void**)&p_bsn, g_bsn);
    cudaGetSymbolAddress((void**)&p_q,   g_q);
    cudaGetSymbolAddress((void**)&p_k,   g_k);
    cudaGetSymbolAddress((void**)&p_v,   g_v);
    cudaGetSymbolAddress((void**)&p_att, g_att);

    static bool attr_done = false;
    if (!attr_done) {
        cudaFuncSetAttribute(attn3, cudaFuncAttributeMaxDynamicSharedMemorySize, 58880);
        attr_done = true;
    }

    const int M = BDIM * SDIM;

    zprep_kernel<<<1, 32>>>(ln_z_w, ln_z_b, w_z);
    adaln_kernel<<<dim3(9, BDIM), 256>>>(t, w_adaln, b_adaln);
    bsnorm_kernel<<<M, 256>>>(bs);

    sgemm2<0><<<dim3(18, M / 128), 256>>>(p_bsn, w_q, w_k, w_v, p_q, p_k, p_v,
                                          rms_q_w, rms_k_w, nullptr);

    zbias2_kernel<<<dim3(SDIM / ZJT, SDIM), 128>>>(z);
    cb_kernel<<<2048, 256>>>(beta, z_mask);

    attn3<<<dim3(SDIM / 64, BDIM * HN), 256, 58880>>>(p_q, p_k, p_v);

    sgemm2<1><<<dim3(6, M / 128), 256>>>(p_att, w_o, nullptr, nullptr, out, nullptr,
                                         nullptr, nullptr, nullptr, b_o);
}

// round 7
// speedup vs baseline: 1.6796x; 1.0107x over previous
#include <cuda_runtime.h>
#include <cstddef>

#define SDIM 1024
#define BDIM 2
#define CS   768
#define CZ   128
#define HN   24
#define DD   32
#define EPSF 1e-5f
#define NEGINF -1000000000.0f
#define LOG2E 1.4426950408889634f

// ---------------- scratch ----------------
__device__ float g_emb[BDIM * 3 * CS];
__device__ float g_bsn[(size_t)BDIM * SDIM * CS];
__device__ float g_q[(size_t)BDIM * SDIM * CS];
__device__ float g_k[(size_t)BDIM * SDIM * CS];
__device__ float g_v[(size_t)BDIM * SDIM * CS];
__device__ float g_zb[(size_t)HN * SDIM * SDIM];   // pre-scaled by LOG2E
__device__ float g_cb[(size_t)BDIM * SDIM * SDIM]; // pre-scaled by LOG2E
__device__ float g_att[(size_t)BDIM * SDIM * CS];
__device__ float g_w1[CZ * HN];
__device__ float g_s12[2 * HN];

// ---------------- f32x2 helpers ----------------
typedef unsigned long long u64;
__device__ __forceinline__ u64 ffma2(u64 a, u64 b, u64 c) {
    u64 d; asm("fma.rn.f32x2 %0,%1,%2,%3;" : "=l"(d) : "l"(a), "l"(b), "l"(c)); return d;
}
__device__ __forceinline__ u64 add2(u64 a, u64 b) {
    u64 d; asm("add.rn.f32x2 %0,%1,%2;" : "=l"(d) : "l"(a), "l"(b)); return d;
}
__device__ __forceinline__ u64 pk2(float a, float b) {
    u64 d; asm("mov.b64 %0,{%1,%2};" : "=l"(d) : "f"(a), "f"(b)); return d;
}
__device__ __forceinline__ float2 up2(u64 v) {
    float2 r; asm("mov.b64 {%0,%1},%2;" : "=f"(r.x), "=f"(r.y) : "l"(v)); return r;
}
__device__ __forceinline__ float ex2(float x) {
    float y; asm("ex2.approx.f32 %0, %1;" : "=f"(y) : "f"(x)); return y;
}

// ---------------- 0. zbias prep ----------------
__global__ void zprep_kernel(const float* __restrict__ lnw, const float* __restrict__ lnb,
                             const float* __restrict__ wz) {
    int h = threadIdx.x;
    if (h >= HN) return;
    float s1 = 0.f, s2 = 0.f;
    for (int c = 0; c < CZ; c++) {
        float w1 = lnw[c] * wz[c * HN + h] * LOG2E;
        g_w1[c * HN + h] = w1;
        s1 += w1;
        s2 += lnb[c] * wz[c * HN + h] * LOG2E;
    }
    g_s12[h] = s1;
    g_s12[HN + h] = s2;
}

// ---------------- 1. adaLN ----------------
__global__ void adaln_kernel(const float* __restrict__ t, const float* __restrict__ w,
                             const float* __restrict__ b) {
    __shared__ float st[CS];
    int bb = blockIdx.y;
    for (int c = threadIdx.x; c < CS; c += 256) {
        float x = t[bb * CS + c];
        st[c] = x / (1.f + __expf(-x));
    }
    __syncthreads();
    int n = blockIdx.x * 256 + threadIdx.x;
    float acc = b[n];
#pragma unroll 4
    for (int c = 0; c < CS; c++) acc += st[c] * w[c * 3 * CS + n];
    g_emb[bb * 3 * CS + n] = acc;
}

// ---------------- 2. bs_norm ----------------
__global__ void bsnorm_kernel(const float* __restrict__ bs) {
    int row = blockIdx.x;
    int bb = row >> 10;
    const float* x = bs + (size_t)row * CS;
    float v[3];
    float s = 0.f, s2 = 0.f;
#pragma unroll
    for (int i = 0; i < 3; i++) {
        v[i] = x[threadIdx.x + i * 256];
        s += v[i]; s2 += v[i] * v[i];
    }
    __shared__ float rs[8], rs2[8], mvar[2];
#pragma unroll
    for (int o = 16; o; o >>= 1) {
        s  += __shfl_xor_sync(~0u, s, o);
        s2 += __shfl_xor_sync(~0u, s2, o);
    }
    int lane = threadIdx.x & 31, warp = threadIdx.x >> 5;
    if (lane == 0) { rs[warp] = s; rs2[warp] = s2; }
    __syncthreads();
    if (threadIdx.x == 0) {
        float a = 0.f, c = 0.f;
#pragma unroll
        for (int i = 0; i < 8; i++) { a += rs[i]; c += rs2[i]; }
        float mu = a * (1.f / CS);
        mvar[0] = mu;
        mvar[1] = rsqrtf(c * (1.f / CS) - mu * mu + EPSF);
    }
    __syncthreads();
    float mu = mvar[0], rstd = mvar[1];
    const float* shift = g_emb + bb * 3 * CS;
    const float* scale = shift + CS;
#pragma unroll
    for (int i = 0; i < 3; i++) {
        int c = threadIdx.x + i * 256;
        g_bsn[(size_t)row * CS + c] = (v[i] - mu) * rstd * (1.f + scale[c]) + shift[c];
    }
}

// ---------------- 3. SGEMM ----------------
template<int MODE>
__global__ __launch_bounds__(256, 2) void sgemm2(
    const float* __restrict__ A,
    const float* __restrict__ W0, const float* __restrict__ W1, const float* __restrict__ W2,
    float* __restrict__ O0, float* __restrict__ O1, float* __restrict__ O2,
    const float* __restrict__ rq, const float* __restrict__ rk,
    const float* __restrict__ bias) {
    __shared__ float As2[2][8][256];
    __shared__ float Bs[2][8][128];
    int tid = threadIdx.x, tx = tid & 15, ty = tid >> 4;
    int mat, nb;
    const float* B; float* O;
    if (MODE == 0) {
        mat = blockIdx.x / 6; nb = blockIdx.x % 6;
        B = (mat == 0) ? W0 : (mat == 1 ? W1 : W2);
        O = (mat == 0) ? O0 : (mat == 1 ? O1 : O2);
    } else { mat = 0; nb = blockIdx.x; B = W0; O = O0; }
    int m0 = blockIdx.y * 128, n0 = nb * 128;
    const int K = CS, N = CS;
    int arow = tid >> 1, acol = (tid & 1) * 4;
    int brow = tid >> 5, bcol = (tid & 31) * 4;
    const float* Ap = A + (size_t)(m0 + arow) * K + acol;
    const float* Bp = B + (size_t)brow * N + n0 + bcol;

    u64 acc[8][4];
#pragma unroll
    for (int i = 0; i < 8; i++)
#pragma unroll
        for (int j = 0; j < 4; j++) acc[i][j] = 0ULL;

    float4 a4 = *(const float4*)Ap;
    float4 b4 = *(const float4*)Bp;
    {
        float va[4] = {a4.x, a4.y, a4.z, a4.w};
#pragma unroll
        for (int w = 0; w < 4; w++)
            *(float2*)&As2[0][acol + w][2 * arow] = make_float2(va[w], va[w]);
        *(float4*)&Bs[0][brow][bcol] = b4;
    }
    __syncthreads();
    int p = 0;
    for (int kt = 8; ; kt += 8) {
        bool more = kt < K;
        if (more) {
            a4 = *(const float4*)(Ap + kt);
            b4 = *(const float4*)(Bp + (size_t)kt * N);
        }
#pragma unroll
        for (int kk = 0; kk < 8; kk++) {
            const float* ar = &As2[p][kk][ty * 16];
            ulonglong2 aA = *(const ulonglong2*)ar;
            ulonglong2 aB = *(const ulonglong2*)(ar + 4);
            ulonglong2 aC = *(const ulonglong2*)(ar + 8);
            ulonglong2 aD = *(const ulonglong2*)(ar + 12);
            const float* br = &Bs[p][kk][tx * 8];
            ulonglong2 bA = *(const ulonglong2*)br;
            ulonglong2 bB = *(const ulonglong2*)(br + 4);
            u64 av[8] = {aA.x, aA.y, aB.x, aB.y, aC.x, aC.y, aD.x, aD.y};
            u64 bv[4] = {bA.x, bA.y, bB.x, bB.y};
#pragma unroll
            for (int i = 0; i < 8; i++)
#pragma unroll
                for (int j = 0; j < 4; j++) acc[i][j] = ffma2(av[i], bv[j], acc[i][j]);
        }
        if (!more) break;
        {
            float va[4] = {a4.x, a4.y, a4.z, a4.w};
#pragma unroll
            for (int w = 0; w < 4; w++)
                *(float2*)&As2[p ^ 1][acol + w][2 * arow] = make_float2(va[w], va[w]);
            *(float4*)&Bs[p ^ 1][brow][bcol] = b4;
        }
        p ^= 1;
        __syncthreads();
    }

    float vout[8][8];
#pragma unroll
    for (int i = 0; i < 8; i++)
#pragma unroll
        for (int jp = 0; jp < 4; jp++) {
            float2 u = up2(acc[i][jp]);
            vout[i][2 * jp] = u.x; vout[i][2 * jp + 1] = u.y;
        }
    if (MODE == 0 && mat < 2) {
        const float* rw = (mat == 0) ? rq : rk;
        float w8[8];
#pragma unroll
        for (int j = 0; j < 8; j++) w8[j] = rw[(tx * 8 + j) & 31];
#pragma unroll
        for (int i = 0; i < 8; i++) {
            float ss = 0.f;
#pragma unroll
            for (int j = 0; j < 8; j++) ss += vout[i][j] * vout[i][j];
            ss += __shfl_xor_sync(~0u, ss, 1);
            ss += __shfl_xor_sync(~0u, ss, 2);
            float r = rsqrtf(ss * (1.f / DD) + EPSF);
#pragma unroll
            for (int j = 0; j < 8; j++) vout[i][j] *= r * w8[j];
        }
    }
    if (MODE == 1) {
#pragma unroll
        for (int i = 0; i < 8; i++) {
            int mrow = m0 + ty * 8 + i;
            const float* gp = g_emb + (mrow >> 10) * 3 * CS + 2 * CS;
#pragma unroll
            for (int j = 0; j < 8; j++) {
                int n = n0 + tx * 8 + j;
                vout[i][j] = (vout[i][j] + bias[n]) * gp[n];
            }
        }
    }
#pragma unroll
    for (int i = 0; i < 8; i++) {
        size_t off = (size_t)(m0 + ty * 8 + i) * N + n0 + tx * 8;
        *(float4*)&O[off]     = *(float4*)&vout[i][0];
        *(float4*)&O[off + 4] = *(float4*)&vout[i][4];
    }
}

// ---------------- 5. z bias v2 ----------------
#define ZJT 512
#define ZKC 8
#define ZPAD 516
__global__ __launch_bounds__(128, 3) void zbias2_kernel(const float* __restrict__ z) {
    __shared__ float zts[ZKC * ZPAD];
    __shared__ float w1s[CZ * HN];
    __shared__ float s12s[2 * HN];
    int i = blockIdx.y, j0 = blockIdx.x * ZJT;
    int t = threadIdx.x;

    {
        const float4* w1g4 = (const float4*)g_w1;
        float4* w1s4 = (float4*)w1s;
#pragma unroll
        for (int u = 0; u < 6; u++) w1s4[u * 128 + t] = w1g4[u * 128 + t];
        if (t < 2 * HN) s12s[t] = g_s12[t];
    }

    const float* zp = z + ((size_t)i * SDIM + j0) * CZ;

    u64 acc[4][12];
#pragma unroll
    for (int jj = 0; jj < 4; jj++)
#pragma unroll
        for (int hp = 0; hp < 12; hp++) acc[jj][hp] = 0ULL;
    u64 sum01 = 0ULL, sum23 = 0ULL, sq01 = 0ULL, sq23 = 0ULL;

    float4 pre[8];
#pragma unroll
    for (int l = 0; l < 8; l++) {
        int idx = l * 128 + t;
        int row = idx >> 1, half = idx & 1;
        pre[l] = *(const float4*)(zp + (size_t)row * CZ + half * 4);
    }

    for (int kt = 0; kt < CZ / ZKC; kt++) {
#pragma unroll
        for (int l = 0; l < 8; l++) {
            int idx = l * 128 + t;
            int row = idx >> 1, half = idx & 1;
            float vv[4] = {pre[l].x, pre[l].y, pre[l].z, pre[l].w};
#pragma unroll
            for (int w = 0; w < 4; w++)
                zts[(half * 4 + w) * ZPAD + row] = vv[w];
        }
        __syncthreads();
        if (kt + 1 < CZ / ZKC) {
            int c0 = (kt + 1) * ZKC;
#pragma unroll
            for (int l = 0; l < 8; l++) {
                int idx = l * 128 + t;
                int row = idx >> 1, half = idx & 1;
                pre[l] = *(const float4*)(zp + (size_t)row * CZ + c0 + half * 4);
            }
        }
#pragma unroll
        for (int c = 0; c < ZKC; c++) {
            int cg = kt * ZKC + c;
            float4 zv = *(const float4*)&zts[c * ZPAD + 4 * t];
            u64 z01 = pk2(zv.x, zv.y), z23 = pk2(zv.z, zv.w);
            sum01 = add2(sum01, z01); sum23 = add2(sum23, z23);
            sq01 = ffma2(z01, z01, sq01); sq23 = ffma2(z23, z23, sq23);
            u64 zd[4];
            zd[0] = pk2(zv.x, zv.x); zd[1] = pk2(zv.y, zv.y);
            zd[2] = pk2(zv.z, zv.z); zd[3] = pk2(zv.w, zv.w);
            const ulonglong2* wr = (const ulonglong2*)&w1s[cg * HN];
            ulonglong2 wA = wr[0], wB = wr[1], wC = wr[2];
            ulonglong2 wD = wr[3], wE = wr[4], wF = wr[5];
            u64 wp[12] = {wA.x, wA.y, wB.x, wB.y, wC.x, wC.y,
                          wD.x, wD.y, wE.x, wE.y, wF.x, wF.y};
#pragma unroll
            for (int jj = 0; jj < 4; jj++)
#pragma unroll
                for (int hp = 0; hp < 12; hp++)
                    acc[jj][hp] = ffma2(zd[jj], wp[hp], acc[jj][hp]);
        }
        __syncthreads();
    }

    float2 s01 = up2(sum01), s23 = up2(sum23);
    float2 q01 = up2(sq01), q23 = up2(sq23);
    float S[4] = {s01.x, s01.y, s23.x, s23.y};
    float Q[4] = {q01.x, q01.y, q23.x, q23.y};
    float mu[4], rstd[4];
#pragma unroll
    for (int jj = 0; jj < 4; jj++) {
        mu[jj] = S[jj] * (1.f / CZ);
        rstd[jj] = rsqrtf(Q[jj] * (1.f / CZ) - mu[jj] * mu[jj] + EPSF);
    }
#pragma unroll
    for (int hp = 0; hp < 12; hp++) {
        float s1a = s12s[2 * hp], s1b = s12s[2 * hp + 1];
        float s2a = s12s[HN + 2 * hp], s2b = s12s[HN + 2 * hp + 1];
        float oa[4], ob[4];
#pragma unroll
        for (int jj = 0; jj < 4; jj++) {
            float2 a = up2(acc[jj][hp]);
            oa[jj] = rstd[jj] * (a.x - mu[jj] * s1a) + s2a;
            ob[jj] = rstd[jj] * (a.y - mu[jj] * s1b) + s2b;
        }
        size_t base_a = (((size_t)(2 * hp) * SDIM + i) * SDIM) + j0 + 4 * t;
        size_t base_b = (((size_t)(2 * hp + 1) * SDIM + i) * SDIM) + j0 + 4 * t;
        *(float4*)&g_zb[base_a] = make_float4(oa[0], oa[1], oa[2], oa[3]);
        *(float4*)&g_zb[base_b] = make_float4(ob[0], ob[1], ob[2], ob[3]);
    }
}

// ---------------- 6. combined bias ----------------
__global__ void cb_kernel(const float* __restrict__ beta, const int* __restrict__ mask) {
    size_t total = (size_t)BDIM * SDIM * SDIM;
    for (size_t idx = (size_t)blockIdx.x * 256 + threadIdx.x; idx < total;
         idx += (size_t)gridDim.x * 256) {
        size_t ij = idx & ((size_t)SDIM * SDIM - 1);
        g_cb[idx] = (beta[idx] + (mask[ij] > 0 ? 0.f : NEGINF)) * LOG2E;
    }
}

// ---------------- 7. flash attention v4b: i-packed, 128x64 tile ----------------
// QT  [32][132]  transposed Q*sc  (128 i + 4 pad)  <-- stride bug fixed
// KT2 [32][136]  transposed K, duplicated along j
// VS2 [64][64]   V duplicated along d
// PT  u64 [64][66]  P packed along i
#define AT_QT  0
#define AT_KT  4224
#define AT_VS  8576
#define AT_PT  12672
#define AT_SMEM_FLOATS 21120   // 84480 bytes
__global__ __launch_bounds__(256, 2) void attn4(const float* __restrict__ q,
                                                const float* __restrict__ k,
                                                const float* __restrict__ v) {
    extern __shared__ float sm[];
    float* QT  = sm + AT_QT;
    float* KT2 = sm + AT_KT;
    float* VS2 = sm + AT_VS;
    u64*   PT  = (u64*)(sm + AT_PT);
    int bh = blockIdx.y, b = bh / HN, h = bh - b * HN;
    int i0 = blockIdx.x * 128;
    int tid = threadIdx.x, tx = tid & 15, ty = tid >> 4;
    const float sc = 0.17677669529663687f * LOG2E;

    const float* qp = q + (size_t)b * SDIM * CS + h * DD;
    const float* kp = k + (size_t)b * SDIM * CS + h * DD;
    const float* vp = v + (size_t)b * SDIM * CS + h * DD;
    const float* zbp = g_zb + (size_t)h * SDIM * SDIM;
    const float* cbp = g_cb + (size_t)b * SDIM * SDIM;

    // load Q transposed (128 rows x 32 d), scaled, no duplication
#pragma unroll
    for (int l = 0; l < 4; l++) {
        int u = tid + l * 256;          // 0..1023
        int r = u >> 3, c4 = u & 7;
        float4 t4 = *(const float4*)(qp + (size_t)(i0 + r) * CS + c4 * 4);
        int d0 = c4 * 4;
        QT[(d0 + 0) * 132 + r] = t4.x * sc;
        QT[(d0 + 1) * 132 + r] = t4.y * sc;
        QT[(d0 + 2) * 132 + r] = t4.z * sc;
        QT[(d0 + 3) * 132 + r] = t4.w * sc;
    }

    u64 acc[4][2];
#pragma unroll
    for (int ip = 0; ip < 4; ip++) { acc[ip][0] = 0ULL; acc[ip][1] = 0ULL; }
    u64 lp2[4] = {0ULL, 0ULL, 0ULL, 0ULL};

    for (int j0 = 0; j0 < SDIM; j0 += 64) {
        // prefetch K,V rows into registers (2 row-chunks per thread)
        float4 kreg[2], vreg[2];
        int ru[2], cu[2];
#pragma unroll
        for (int l = 0; l < 2; l++) {
            int u = tid + l * 256;      // 0..511
            ru[l] = u >> 3; cu[l] = u & 7;
            kreg[l] = *(const float4*)(kp + (size_t)(j0 + ru[l]) * CS + cu[l] * 4);
            vreg[l] = *(const float4*)(vp + (size_t)(j0 + ru[l]) * CS + cu[l] * 4);
        }
        // bias -> s (packed along i): s[ip][jj] = (bias_i0, bias_i1)
        u64 s[4][4];
#pragma unroll
        for (int ip = 0; ip < 4; ip++) {
            int ia = i0 + ty * 8 + 2 * ip, ib = ia + 1;
            size_t roa = (size_t)ia * SDIM + j0 + tx * 4;
            size_t rob = (size_t)ib * SDIM + j0 + tx * 4;
            float4 za = *(const float4*)(zbp + roa);
            float4 zb = *(const float4*)(zbp + rob);
            float4 ca = *(const float4*)(cbp + roa);
            float4 cb = *(const float4*)(cbp + rob);
            s[ip][0] = add2(pk2(za.x, zb.x), pk2(ca.x, cb.x));
            s[ip][1] = add2(pk2(za.y, zb.y), pk2(ca.y, cb.y));
            s[ip][2] = add2(pk2(za.z, zb.z), pk2(ca.z, cb.z));
            s[ip][3] = add2(pk2(za.w, zb.w), pk2(ca.w, cb.w));
        }
        __syncthreads();   // prior-tile PV readers done; safe to overwrite KT2/VS2
        // store K (transposed + dup'd), V (dup'd)
#pragma unroll
        for (int l = 0; l < 2; l++) {
            int r = ru[l], d0 = cu[l] * 4;
            float kv[4] = {kreg[l].x, kreg[l].y, kreg[l].z, kreg[l].w};
            float vv[4] = {vreg[l].x, vreg[l].y, vreg[l].z, vreg[l].w};
#pragma unroll
            for (int w = 0; w < 4; w++) {
                *(float2*)&KT2[(d0 + w) * 136 + 2 * r] = make_float2(kv[w], kv[w]);
                *(float2*)&VS2[r * 64 + (d0 + w) * 2] = make_float2(vv[w], vv[w]);
            }
        }
        __syncthreads();

        // QK^T
#pragma unroll 8
        for (int kk = 0; kk < DD; kk++) {
            const ulonglong2* qr = (const ulonglong2*)&QT[kk * 132 + ty * 8];
            ulonglong2 qA = qr[0], qB = qr[1];      // natural (i,i+1) pairs
            const ulonglong2* kr = (const ulonglong2*)&KT2[kk * 136 + tx * 8];
            ulonglong2 kA = kr[0], kB = kr[1];      // dup'd j
            u64 a[4] = {qA.x, qA.y, qB.x, qB.y};
            u64 bj[4] = {kA.x, kA.y, kB.x, kB.y};
#pragma unroll
            for (int ip = 0; ip < 4; ip++)
#pragma unroll
                for (int jj = 0; jj < 4; jj++)
                    s[ip][jj] = ffma2(a[ip], bj[jj], s[ip][jj]);
        }

        // p = exp2(s); accumulate packed row sums; store P (i-packed) to smem
#pragma unroll
        for (int ip = 0; ip < 4; ip++) {
            u64 p[4];
#pragma unroll
            for (int jj = 0; jj < 4; jj++) {
                float2 sv = up2(s[ip][jj]);
                p[jj] = pk2(ex2(sv.x), ex2(sv.y));
            }
            lp2[ip] = add2(lp2[ip], add2(add2(p[0], p[1]), add2(p[2], p[3])));
            int ipg = ty * 4 + ip;
#pragma unroll
            for (int jj = 0; jj < 4; jj++)
                PT[(tx * 4 + jj) * 66 + ipg] = p[jj];
        }
        __syncthreads();

        // P @ V
#pragma unroll 8
        for (int kk = 0; kk < 64; kk++) {
            const ulonglong2* pr = (const ulonglong2*)&PT[kk * 66 + ty * 4];
            ulonglong2 pA = pr[0], pB = pr[1];
            ulonglong2 vv = *(const ulonglong2*)&VS2[kk * 64 + tx * 4];
            u64 p4[4] = {pA.x, pA.y, pB.x, pB.y};
#pragma unroll
            for (int ip = 0; ip < 4; ip++) {
                acc[ip][0] = ffma2(p4[ip], vv.x, acc[ip][0]);
                acc[ip][1] = ffma2(p4[ip], vv.y, acc[ip][1]);
            }
        }
    }

    // reduce packed row sums across the 16 tx lanes
    float lpa[4], lpb[4];
#pragma unroll
    for (int ip = 0; ip < 4; ip++) {
        float2 u = up2(lp2[ip]);
        lpa[ip] = u.x; lpb[ip] = u.y;
#pragma unroll
        for (int o = 8; o; o >>= 1) {
            lpa[ip] += __shfl_xor_sync(~0u, lpa[ip], o);
            lpb[ip] += __shfl_xor_sync(~0u, lpb[ip], o);
        }
    }
#pragma unroll
    for (int ip = 0; ip < 4; ip++) {
        float inva = 1.f / lpa[ip], invb = 1.f / lpb[ip];
        float2 d0 = up2(acc[ip][0]);    // (out_i0_d0, out_i1_d0)
        float2 d1 = up2(acc[ip][1]);
        int ia = i0 + ty * 8 + 2 * ip;
        size_t oa = ((size_t)b * SDIM + ia) * CS + h * DD + tx * 2;
        *(float2*)&g_att[oa]      = make_float2(d0.x * inva, d1.x * inva);
        *(float2*)&g_att[oa + CS] = make_float2(d0.y * invb, d1.y * invb);
    }
}

// ---------------- launch ----------------
extern "C" void kernel_launch(void* const* d_in, const int* in_sizes, int n_in,
                              void* d_out, int out_size) {
    const float* bs      = (const float*)d_in[0];
    const float* z       = (const float*)d_in[1];
    const float* t       = (const float*)d_in[2];
    const float* beta    = (const float*)d_in[3];
    const int*   z_mask  = (const int*)d_in[4];
    const float* w_adaln = (const float*)d_in[5];
    const float* b_adaln = (const float*)d_in[6];
    const float* ln_z_w  = (const float*)d_in[7];
    const float* ln_z_b  = (const float*)d_in[8];
    const float* w_q     = (const float*)d_in[9];
    const float* w_k     = (const float*)d_in[10];
    const float* w_v     = (const float*)d_in[11];
    const float* w_z     = (const float*)d_in[12];
    const float* rms_q_w = (const float*)d_in[13];
    const float* rms_k_w = (const float*)d_in[14];
    const float* w_o     = (const float*)d_in[15];
    const float* b_o     = (const float*)d_in[16];
    float* out = (float*)d_out;

    float *p_bsn, *p_q, *p_k, *p_v, *p_att;
    cudaGetSymbolAddress((void**)&p_bsn, g_bsn);
    cudaGetSymbolAddress((void**)&p_q,   g_q);
    cudaGetSymbolAddress((void**)&p_k,   g_k);
    cudaGetSymbolAddress((void**)&p_v,   g_v);
    cudaGetSymbolAddress((void**)&p_att, g_att);

    static bool attr_done = false;
    if (!attr_done) {
        cudaFuncSetAttribute(attn4, cudaFuncAttributeMaxDynamicSharedMemorySize,
                             AT_SMEM_FLOATS * 4);
        attr_done = true;
    }

    const int M = BDIM * SDIM;

    zprep_kernel<<<1, 32>>>(ln_z_w, ln_z_b, w_z);
    adaln_kernel<<<dim3(9, BDIM), 256>>>(t, w_adaln, b_adaln);
    bsnorm_kernel<<<M, 256>>>(bs);

    sgemm2<0><<<dim3(18, M / 128), 256>>>(p_bsn, w_q, w_k, w_v, p_q, p_k, p_v,
                                          rms_q_w, rms_k_w, nullptr);

    zbias2_kernel<<<dim3(SDIM / ZJT, SDIM), 128>>>(z);
    cb_kernel<<<2048, 256>>>(beta, z_mask);

    attn4<<<dim3(SDIM / 128, BDIM * HN), 256, AT_SMEM_FLOATS * 4>>>(p_q, p_k, p_v);

    sgemm2<1><<<dim3(6, M / 128), 256>>>(p_att, w_o, nullptr, nullptr, out, nullptr,
                                         nullptr, nullptr, nullptr, b_o);
}